// round 9
// baseline (speedup 1.0000x reference)
#include <cuda_runtime.h>
#include <math.h>

// ---------------------------------------------------------------------------
// Problem constants
// ---------------------------------------------------------------------------
#define NB   1024
#define NC   32
#define LIN  1024
#define LRAW 1041
#define LP   520
#define L1   257
#define L2   125
#define L3   31
#define L4   12
#define ZDIM 768

// ---------------------------------------------------------------------------
// Scratch
// ---------------------------------------------------------------------------
__device__ float  g_filt[NC * 16];
__device__ float  g_hp[NB * NC * LP];
__device__ double g_st1[2 * NC];
__device__ double g_st2[2 * NC];
__device__ double g_st3[2 * NC];
__device__ float  g_y1[NB * NC * L3];
__device__ float  g_y2[NB * NC * L3];
__device__ float  g_z [NB * ZDIM];
__device__ float  g_c1[NB * 1024];
__device__ float  g_c2[NB * 512];
__device__ float  g_c3[NB * 128];

// packed f32x2 FMA: d.lo += a.lo*b.lo ; d.hi += a.hi*b.hi (accumulate form)
#define FFMA2(d, a, b) \
    asm volatile("fma.rn.f32x2 %0, %1, %2, %0;" : "+l"(d) : "l"(a), "l"(b))

// ---------------------------------------------------------------------------
// K0: zero stats + build Laplace filter bank
// ---------------------------------------------------------------------------
__global__ void k_init(const float* __restrict__ la_a, const float* __restrict__ la_b) {
    int t = threadIdx.x;
    if (t < 2 * NC) { g_st1[t] = 0.0; g_st2[t] = 0.0; g_st3[t] = 0.0; }
    if (t < NC * 16) {
        int c = t >> 4, k = t & 15;
        const double A = 0.08, ep = 0.03, tal = 0.1, f = 50.0;
        const double w = 2.0 * 3.14159265358979323846 * f;
        const double q = 1.0 - ep * ep;
        double tk = (double)k / 15.0;
        double p  = tk - (double)la_b[c] / (double)la_a[c];
        double arg = w * (p - tal);
        double y = A * exp(-ep / sqrt(q) * arg) * (-sin(arg));
        g_filt[t] = (float)y;
    }
}

// ---------------------------------------------------------------------------
// K1: conv (pad 16/16) + la_bias + BN1 stats + avgpool(3,2)  -> g_hp
// ---------------------------------------------------------------------------
__global__ __launch_bounds__(256) void k_conv(const float* __restrict__ x,
                                              const float* __restrict__ la_bias) {
    __shared__ float sxp[1060];

    int b = blockIdx.x;
    int t = threadIdx.x;

    for (int i = t; i < 1060; i += 256) {
        int xi = i - 16;
        sxp[i] = (xi >= 0 && xi < LIN) ? x[b * LIN + xi] : 0.0f;
    }
    __syncthreads();

    int w = t >> 5, lane = t & 31;

    #pragma unroll 1
    for (int cc = 0; cc < 4; cc++) {
        int c = w * 4 + cc;
        float f[16];
        #pragma unroll
        for (int k = 0; k < 16; k++) f[k] = g_filt[c * 16 + k];
        float bias = la_bias[c];

        float s = 0.0f, ss = 0.0f;
        float* hprow = &g_hp[(b * NC + c) * LP];

        #pragma unroll 1
        for (int i = 0; i < 9; i++) {
            int base = 4 * lane + 128 * i;
            if (base > 1040) continue;
            float win[20];
            #pragma unroll
            for (int j = 0; j < 5; j++) {
                float4 q = *reinterpret_cast<const float4*>(&sxp[base + 4 * j]);
                win[4 * j + 0] = q.x; win[4 * j + 1] = q.y;
                win[4 * j + 2] = q.z; win[4 * j + 3] = q.w;
            }
            float r0 = bias, r1 = bias, r2 = bias, r3 = bias, r4 = bias;
            #pragma unroll
            for (int k = 0; k < 16; k++) {
                float fk = f[k];
                r0 = fmaf(win[k    ], fk, r0);
                r1 = fmaf(win[k + 1], fk, r1);
                r2 = fmaf(win[k + 2], fk, r2);
                r3 = fmaf(win[k + 3], fk, r3);
                r4 = fmaf(win[k + 4], fk, r4);
            }
            if (base + 0 <= 1040) { s += r0; ss = fmaf(r0, r0, ss); }
            if (base + 1 <= 1040) { s += r1; ss = fmaf(r1, r1, ss); }
            if (base + 2 <= 1040) { s += r2; ss = fmaf(r2, r2, ss); }
            if (base + 3 <= 1040) { s += r3; ss = fmaf(r3, r3, ss); }
            int m0 = base >> 1;
            if (m0 <= 518) {
                float2 pv;
                pv.x = (r0 + r1 + r2) * (1.0f / 3.0f);
                pv.y = (r2 + r3 + r4) * (1.0f / 3.0f);
                *reinterpret_cast<float2*>(&hprow[m0]) = pv;
            }
        }
        #pragma unroll
        for (int o = 16; o > 0; o >>= 1) {
            s  += __shfl_down_sync(0xffffffffu, s,  o);
            ss += __shfl_down_sync(0xffffffffu, ss, o);
        }
        if (lane == 0) {
            atomicAdd(&g_st1[c],      (double)s);
            atomicAdd(&g_st1[NC + c], (double)ss);
        }
    }
}

// ---------------------------------------------------------------------------
// K3: both branches. BN1 folded into layer-1 weights (computed inline from
// stats), cp.async double-buffered prefetch of next channel's g_hp row.
// ---------------------------------------------------------------------------
__global__ __launch_bounds__(256) void k_branch(
    const float* __restrict__ bn1_g, const float* __restrict__ bn1_b,
    const float* __restrict__ a1_w, const float* __restrict__ a1_b,
    const float* __restrict__ e1_w, const float* __restrict__ e1_b,
    const float* __restrict__ f1_w, const float* __restrict__ f1_b,
    const float* __restrict__ fa_w, const float* __restrict__ fa_b) {

    // per warp: in[2][528] double buffer + s1[264] + pad -> 1328 floats
    __shared__ float sh[8][1328];

    int b = blockIdx.x;
    int t = threadIdx.x;
    int w = t >> 5, lane = t & 31;

    unsigned sbase = (unsigned)__cvta_generic_to_shared(&sh[0][0]);
    unsigned in_u32[2] = { sbase + (unsigned)(w * 1328) * 4u,
                           sbase + (unsigned)(w * 1328 + 528) * 4u };
    const float* inptr[2] = { &sh[w][0], &sh[w][528] };
    float* s1 = &sh[w][1056];

    int cbase = w * 4;

    // preload channel cbase into buf 0
    {
        const float* src = &g_hp[(b * NC + cbase) * LP];
        #pragma unroll
        for (int i = 0; i < 5; i++) {
            int idx = lane + 32 * i;
            if (idx < 130)
                asm volatile("cp.async.ca.shared.global [%0], [%1], 16;"
                             :: "r"(in_u32[0] + idx * 16), "l"(src + idx * 4));
        }
        asm volatile("cp.async.commit_group;" ::: "memory");
    }

    #pragma unroll
    for (int cc = 0; cc < 4; cc++) {
        int c = cbase + cc;
        if (cc < 3) {
            const float* src = &g_hp[(b * NC + c + 1) * LP];
            unsigned dst = in_u32[(cc + 1) & 1];
            #pragma unroll
            for (int i = 0; i < 5; i++) {
                int idx = lane + 32 * i;
                if (idx < 130)
                    asm volatile("cp.async.ca.shared.global [%0], [%1], 16;"
                                 :: "r"(dst + idx * 16), "l"(src + idx * 4));
            }
            asm volatile("cp.async.commit_group;" ::: "memory");
            asm volatile("cp.async.wait_group 1;" ::: "memory");
        } else {
            asm volatile("cp.async.wait_group 0;" ::: "memory");
        }
        __syncwarp();
        const float* in = inptr[cc & 1];

        // BN1 affine (inline from stats), to be folded into layer-1 weights
        double Nn = (double)NB * (double)LRAW;
        double m = g_st1[c] / Nn;
        double var = g_st1[NC + c] / Nn - m * m;
        float sc = bn1_g[c] * rsqrtf((float)var + 1e-5f);
        float sf = bn1_b[c] - (float)m * sc;

        #pragma unroll 1
        for (int br = 0; br < 2; br++) {
            // layer-1 weights/bias with BN1 folded in:
            //   r = base_acc + sf*sum(w) + sum((sc*w)_j * hp_j)
            float w1r[8], acc1;
            {
                const float* wsrc = (br == 0) ? &a1_w[c * 8] : &f1_w[c * 8];
                float sum = 0.0f;
                #pragma unroll
                for (int j = 0; j < 8; j++) { w1r[j] = wsrc[j]; sum += w1r[j]; }
                float base = (br == 0) ? (a1_b[c] - sum) : (1.0f - f1_b[c]);
                acc1 = base + sf * sum;
                #pragma unroll
                for (int j = 0; j < 8; j++) w1r[j] *= sc;
            }

            // layer 1: 256 outputs
            #pragma unroll
            for (int i = 0; i < 2; i++) {
                int n0 = 4 * lane + 128 * i;
                int base = 2 * n0;
                float win[16];
                #pragma unroll
                for (int j = 0; j < 4; j++) {
                    float4 q = *reinterpret_cast<const float4*>(&in[base + 4 * j]);
                    win[4 * j + 0] = q.x; win[4 * j + 1] = q.y;
                    win[4 * j + 2] = q.z; win[4 * j + 3] = q.w;
                }
                float r0 = acc1, r1 = acc1, r2 = acc1, r3 = acc1;
                #pragma unroll
                for (int k = 0; k < 8; k++) {
                    float wk = w1r[k];
                    r0 = fmaf(win[k    ], wk, r0);
                    r1 = fmaf(win[k + 2], wk, r1);
                    r2 = fmaf(win[k + 4], wk, r2);
                    r3 = fmaf(win[k + 6], wk, r3);
                }
                float4 o;
                o.x = fmaxf(r0, 0.0f); o.y = fmaxf(r1, 0.0f);
                o.z = fmaxf(r2, 0.0f); o.w = fmaxf(r3, 0.0f);
                *reinterpret_cast<float4*>(&s1[n0]) = o;
            }
            __syncwarp();

            // layer-2 weights/bias
            float w2r[8], acc2;
            if (br == 0) {
                #pragma unroll
                for (int j = 0; j < 8; j++) w2r[j] = e1_w[c * 8 + j];
                acc2 = 1.0f - e1_b[c];
            } else {
                float sum = 0.0f;
                #pragma unroll
                for (int j = 0; j < 8; j++) { w2r[j] = fa_w[c * 8 + j]; sum += w2r[j]; }
                acc2 = fa_b[c] - sum;
            }

            // layer 2 + maxpool(4,4) in registers
            {
                int base = 8 * lane;
                float win[16];
                #pragma unroll
                for (int j = 0; j < 4; j++) {
                    float4 q = *reinterpret_cast<const float4*>(&s1[base + 4 * j]);
                    win[4 * j + 0] = q.x; win[4 * j + 1] = q.y;
                    win[4 * j + 2] = q.z; win[4 * j + 3] = q.w;
                }
                float r0 = acc2, r1 = acc2, r2 = acc2, r3 = acc2;
                #pragma unroll
                for (int k = 0; k < 8; k++) {
                    float wk = w2r[k];
                    r0 = fmaf(win[k    ], wk, r0);
                    r1 = fmaf(win[k + 2], wk, r1);
                    r2 = fmaf(win[k + 4], wk, r2);
                    r3 = fmaf(win[k + 6], wk, r3);
                }
                r0 = fmaxf(r0, 0.0f); r1 = fmaxf(r1, 0.0f);
                r2 = fmaxf(r2, 0.0f); r3 = fmaxf(r3, 0.0f);
                float y = fmaxf(fmaxf(r0, r1), fmaxf(r2, r3));
                float s = 0.0f, ss = 0.0f;
                if (lane < L3) {
                    if (br == 0) g_y1[(b * NC + c) * L3 + lane] = y;
                    else         g_y2[(b * NC + c) * L3 + lane] = y;
                    s = y; ss = y * y;
                }
                #pragma unroll
                for (int o = 16; o > 0; o >>= 1) {
                    s  += __shfl_down_sync(0xffffffffu, s,  o);
                    ss += __shfl_down_sync(0xffffffffu, ss, o);
                }
                if (lane == 0) {
                    double* st = (br == 0) ? g_st2 : g_st3;
                    atomicAdd(&st[c],      (double)s);
                    atomicAdd(&st[NC + c], (double)ss);
                }
            }
            __syncwarp();
        }
    }
}

// ---------------------------------------------------------------------------
// K5: BN2/BN3 (inline from stats) + final Eventually -> z (B,768)
// ---------------------------------------------------------------------------
__global__ __launch_bounds__(256) void k_zassm(
    const float* __restrict__ e2_w, const float* __restrict__ e2_b,
    const float* __restrict__ f2_w, const float* __restrict__ f2_b,
    const float* __restrict__ bn2_g, const float* __restrict__ bn2_b,
    const float* __restrict__ bn3_g, const float* __restrict__ bn3_b) {
    __shared__ float ssc[2][NC], ssh[2][NC];
    int b = blockIdx.x;
    int t = threadIdx.x;
    if (t < 64) {
        int br = t >> 5, c = t & 31;
        const double* st = br ? g_st3 : g_st2;
        float gam = br ? bn3_g[c] : bn2_g[c];
        float bet = br ? bn3_b[c] : bn2_b[c];
        double Nn = (double)NB * (double)L3;
        double m = st[c] / Nn;
        double v = st[NC + c] / Nn - m * m;
        float sc = gam * rsqrtf((float)v + 1e-5f);
        ssc[br][c] = sc;
        ssh[br][c] = bet - (float)m * sc;
    }
    __syncthreads();

    for (int o = t; o < ZDIM; o += 256) {
        int br  = o / 384;
        int rem = o - br * 384;
        int c = rem / L4, n = rem - c * L4;
        const float* y  = br ? &g_y2[(b * NC + c) * L3] : &g_y1[(b * NC + c) * L3];
        const float* wv = br ? &f2_w[c * 8] : &e2_w[c * 8];
        float bb = br ? f2_b[c] : e2_b[c];
        float scv = ssc[br][c], shv = ssh[br][c];
        float acc = 1.0f - bb;
        #pragma unroll
        for (int j = 0; j < 8; j++)
            acc = fmaf(fmaf(y[2 * n + j], scv, shv), wv[j], acc);
        g_z[b * ZDIM + o] = fmaxf(acc, 0.0f);
    }
}

// ---------------------------------------------------------------------------
// Tiled fp32 GEMM with packed f32x2 FMA, fused bias+relu.
// C = relu(A[MxK] @ W[KxN] + bias). BN fixed at 64, BM template (64/128),
// THREADS = 2*BM, micro-tile 8 rows (4 packed pairs) x 4 cols.
// W stored DUPLICATED in smem so w-pairs load pre-packed. K%16==0.
// ---------------------------------------------------------------------------
template<int BM>
__global__ __launch_bounds__(2 * BM) void k_gemm_relu(
    const float* __restrict__ A, const float* __restrict__ W,
    const float* __restrict__ bias, float* __restrict__ Cc,
    int M, int N, int K) {
    constexpr int THREADS = 2 * BM;
    constexpr int WLOADS  = 128 / BM;     // float4s of W per thread per tile
    __shared__ float As[16][BM + 4];      // [k][m] transposed
    __shared__ float Wd[16][128];         // [k][2n] duplicated pairs

    int tid = threadIdx.x;
    int tx = tid & 15, ty = tid >> 4;
    int rowBase = blockIdx.y * BM;
    int colBase = blockIdx.x * 64;

    // A loader: 2 float4 per thread
    int aRow[2], aC4[2];
    const float* Ap[2];
    #pragma unroll
    for (int i = 0; i < 2; i++) {
        int idx = tid + i * THREADS;
        aRow[i] = idx >> 2;
        aC4[i]  = (idx & 3) * 4;
        Ap[i] = A + (rowBase + aRow[i]) * K + aC4[i];
    }
    // W loader
    int wRow[WLOADS], wCol[WLOADS];
    const float* Wp[WLOADS];
    #pragma unroll
    for (int i = 0; i < WLOADS; i++) {
        int idx = tid + i * THREADS;
        wRow[i] = idx >> 4;
        wCol[i] = (idx & 15) * 4;
        Wp[i] = W + wRow[i] * N + colBase + wCol[i];
    }

    float4 avr[2], wvr[WLOADS];
    #pragma unroll
    for (int i = 0; i < 2; i++) avr[i] = *reinterpret_cast<const float4*>(Ap[i]);
    #pragma unroll
    for (int i = 0; i < WLOADS; i++) wvr[i] = *reinterpret_cast<const float4*>(Wp[i]);

    unsigned long long acc[4][4];
    #pragma unroll
    for (int i = 0; i < 4; i++)
        #pragma unroll
        for (int j = 0; j < 4; j++) acc[i][j] = 0ull;

    for (int kt = 0; kt < K; kt += 16) {
        __syncthreads();
        #pragma unroll
        for (int i = 0; i < 2; i++) {
            As[aC4[i] + 0][aRow[i]] = avr[i].x;
            As[aC4[i] + 1][aRow[i]] = avr[i].y;
            As[aC4[i] + 2][aRow[i]] = avr[i].z;
            As[aC4[i] + 3][aRow[i]] = avr[i].w;
        }
        #pragma unroll
        for (int i = 0; i < WLOADS; i++) {
            float4 v = wvr[i];
            float4 lo = make_float4(v.x, v.x, v.y, v.y);
            float4 hi = make_float4(v.z, v.z, v.w, v.w);
            *reinterpret_cast<float4*>(&Wd[wRow[i]][2 * wCol[i]])     = lo;
            *reinterpret_cast<float4*>(&Wd[wRow[i]][2 * wCol[i] + 4]) = hi;
        }
        __syncthreads();
        if (kt + 16 < K) {
            #pragma unroll
            for (int i = 0; i < 2; i++)
                avr[i] = *reinterpret_cast<const float4*>(Ap[i] + kt + 16);
            #pragma unroll
            for (int i = 0; i < WLOADS; i++)
                wvr[i] = *reinterpret_cast<const float4*>(Wp[i] + (kt + 16) * N);
        }
        #pragma unroll
        for (int k = 0; k < 16; k++) {
            ulonglong2 aA = *reinterpret_cast<const ulonglong2*>(&As[k][ty * 8]);
            ulonglong2 aB = *reinterpret_cast<const ulonglong2*>(&As[k][ty * 8 + 4]);
            ulonglong2 wA = *reinterpret_cast<const ulonglong2*>(&Wd[k][tx * 8]);
            ulonglong2 wB = *reinterpret_cast<const ulonglong2*>(&Wd[k][tx * 8 + 4]);
            unsigned long long ap[4] = { aA.x, aA.y, aB.x, aB.y };
            unsigned long long wp[4] = { wA.x, wA.y, wB.x, wB.y };
            #pragma unroll
            for (int mi = 0; mi < 4; mi++)
                #pragma unroll
                for (int j = 0; j < 4; j++)
                    FFMA2(acc[mi][j], ap[mi], wp[j]);
        }
    }

    float4 bv = *reinterpret_cast<const float4*>(&bias[colBase + tx * 4]);
    float bj[4] = { bv.x, bv.y, bv.z, bv.w };
    #pragma unroll
    for (int mi = 0; mi < 4; mi++) {
        int r0 = rowBase + ty * 8 + 2 * mi;
        float4 o0, o1;
        float lo[4], hi[4];
        #pragma unroll
        for (int j = 0; j < 4; j++) {
            lo[j] = __uint_as_float((unsigned)(acc[mi][j] & 0xffffffffull));
            hi[j] = __uint_as_float((unsigned)(acc[mi][j] >> 32));
        }
        o0.x = fmaxf(lo[0] + bj[0], 0.0f); o0.y = fmaxf(lo[1] + bj[1], 0.0f);
        o0.z = fmaxf(lo[2] + bj[2], 0.0f); o0.w = fmaxf(lo[3] + bj[3], 0.0f);
        o1.x = fmaxf(hi[0] + bj[0], 0.0f); o1.y = fmaxf(hi[1] + bj[1], 0.0f);
        o1.z = fmaxf(hi[2] + bj[2], 0.0f); o1.w = fmaxf(hi[3] + bj[3], 0.0f);
        *reinterpret_cast<float4*>(&Cc[r0 * N + colBase + tx * 4])       = o0;
        *reinterpret_cast<float4*>(&Cc[(r0 + 1) * N + colBase + tx * 4]) = o1;
    }
}

// ---------------------------------------------------------------------------
// Final FC: (B,128) @ (128,10) + bias, relu. One warp per batch row.
// ---------------------------------------------------------------------------
__global__ __launch_bounds__(256) void k_fc4(const float* __restrict__ w4,
                                             const float* __restrict__ b4,
                                             float* __restrict__ out) {
    int b = blockIdx.x * 8 + (threadIdx.x >> 5);
    int lane = threadIdx.x & 31;
    const float* row = &g_c3[b * 128];
    float v0 = row[lane], v1 = row[lane + 32], v2 = row[lane + 64], v3 = row[lane + 96];
    for (int j = 0; j < 10; j++) {
        float p = v0 * w4[lane * 10 + j]
                + v1 * w4[(lane + 32) * 10 + j]
                + v2 * w4[(lane + 64) * 10 + j]
                + v3 * w4[(lane + 96) * 10 + j];
        #pragma unroll
        for (int o = 16; o > 0; o >>= 1) p += __shfl_down_sync(0xffffffffu, p, o);
        if (lane == 0) out[b * 10 + j] = fmaxf(p + b4[j], 0.0f);
    }
}

// ---------------------------------------------------------------------------
// Launch
// ---------------------------------------------------------------------------
extern "C" void kernel_launch(void* const* d_in, const int* in_sizes, int n_in,
                              void* d_out, int out_size) {
    const float* x       = (const float*)d_in[0];
    const float* la_a    = (const float*)d_in[1];
    const float* la_b    = (const float*)d_in[2];
    const float* la_bias = (const float*)d_in[3];
    const float* bn1_g   = (const float*)d_in[4];
    const float* bn1_b   = (const float*)d_in[5];
    const float* a1_w    = (const float*)d_in[6];
    const float* a1_b    = (const float*)d_in[7];
    const float* e1_w    = (const float*)d_in[8];
    const float* e1_b    = (const float*)d_in[9];
    const float* bn2_g   = (const float*)d_in[10];
    const float* bn2_b   = (const float*)d_in[11];
    const float* e2_w    = (const float*)d_in[12];
    const float* e2_b    = (const float*)d_in[13];
    const float* f1_w    = (const float*)d_in[14];
    const float* f1_b    = (const float*)d_in[15];
    const float* fa_w    = (const float*)d_in[16];
    const float* fa_b    = (const float*)d_in[17];
    const float* bn3_g   = (const float*)d_in[18];
    const float* bn3_b   = (const float*)d_in[19];
    const float* f2_w    = (const float*)d_in[20];
    const float* f2_b    = (const float*)d_in[21];
    const float* w1      = (const float*)d_in[22];
    const float* b1      = (const float*)d_in[23];
    const float* w2      = (const float*)d_in[24];
    const float* b2      = (const float*)d_in[25];
    const float* w3      = (const float*)d_in[26];
    const float* b3      = (const float*)d_in[27];
    const float* w4      = (const float*)d_in[28];
    const float* b4      = (const float*)d_in[29];
    float* out = (float*)d_out;

    float *p_z = nullptr, *p_c1 = nullptr, *p_c2 = nullptr, *p_c3 = nullptr;
    cudaGetSymbolAddress((void**)&p_z,  g_z);
    cudaGetSymbolAddress((void**)&p_c1, g_c1);
    cudaGetSymbolAddress((void**)&p_c2, g_c2);
    cudaGetSymbolAddress((void**)&p_c3, g_c3);

    k_init<<<1, 512>>>(la_a, la_b);
    k_conv<<<NB, 256>>>(x, la_bias);
    k_branch<<<NB, 256>>>(bn1_g, bn1_b, a1_w, a1_b, e1_w, e1_b,
                          f1_w, f1_b, fa_w, fa_b);
    k_zassm<<<NB, 256>>>(e2_w, e2_b, f2_w, f2_b, bn2_g, bn2_b, bn3_g, bn3_b);

    {   // 1024x1024x768
        dim3 g(1024 / 64, NB / 128);
        k_gemm_relu<128><<<g, 256>>>(p_z, w1, b1, p_c1, NB, 1024, 768);
    }
    {   // 1024x512x1024
        dim3 g(512 / 64, NB / 64);
        k_gemm_relu<64><<<g, 128>>>(p_c1, w2, b2, p_c2, NB, 512, 1024);
    }
    {   // 1024x128x512
        dim3 g(128 / 64, NB / 64);
        k_gemm_relu<64><<<g, 128>>>(p_c2, w3, b3, p_c3, NB, 128, 512);
    }
    k_fc4<<<NB / 8, 256>>>(w4, b4, out);
}

// round 10
// speedup vs baseline: 1.3178x; 1.3178x over previous
#include <cuda_runtime.h>
#include <math.h>

// ---------------------------------------------------------------------------
// Problem constants
// ---------------------------------------------------------------------------
#define NB   1024
#define NC   32
#define LIN  1024
#define LRAW 1041
#define LP   520
#define L1   257
#define L2   125
#define L3   31
#define L4   12
#define ZDIM 768

// ---------------------------------------------------------------------------
// Scratch
// ---------------------------------------------------------------------------
__device__ float  g_filt[NC * 16];
__device__ float  g_hp[NB * NC * LP];
__device__ double g_st1[2 * NC];
__device__ double g_st2[2 * NC];
__device__ double g_st3[2 * NC];
__device__ float  g_y1[NB * NC * L3];
__device__ float  g_y2[NB * NC * L3];
__device__ float  g_z [NB * ZDIM];
__device__ float  g_c1[NB * 1024];
__device__ float  g_c2[NB * 512];
__device__ float  g_c3[NB * 128];

// ---------------------------------------------------------------------------
// K0: zero stats + build Laplace filter bank
// ---------------------------------------------------------------------------
__global__ void k_init(const float* __restrict__ la_a, const float* __restrict__ la_b) {
    int t = threadIdx.x;
    if (t < 2 * NC) { g_st1[t] = 0.0; g_st2[t] = 0.0; g_st3[t] = 0.0; }
    if (t < NC * 16) {
        int c = t >> 4, k = t & 15;
        const double A = 0.08, ep = 0.03, tal = 0.1, f = 50.0;
        const double w = 2.0 * 3.14159265358979323846 * f;
        const double q = 1.0 - ep * ep;
        double tk = (double)k / 15.0;
        double p  = tk - (double)la_b[c] / (double)la_a[c];
        double arg = w * (p - tal);
        double y = A * exp(-ep / sqrt(q) * arg) * (-sin(arg));
        g_filt[t] = (float)y;
    }
}

// ---------------------------------------------------------------------------
// K1: conv (pad 16/16) + la_bias + BN1 stats + avgpool(3,2)  -> g_hp
// ---------------------------------------------------------------------------
__global__ __launch_bounds__(256) void k_conv(const float* __restrict__ x,
                                              const float* __restrict__ la_bias) {
    __shared__ float sxp[1060];

    int b = blockIdx.x;
    int t = threadIdx.x;

    for (int i = t; i < 1060; i += 256) {
        int xi = i - 16;
        sxp[i] = (xi >= 0 && xi < LIN) ? x[b * LIN + xi] : 0.0f;
    }
    __syncthreads();

    int w = t >> 5, lane = t & 31;

    #pragma unroll 1
    for (int cc = 0; cc < 4; cc++) {
        int c = w * 4 + cc;
        float f[16];
        #pragma unroll
        for (int k = 0; k < 16; k++) f[k] = g_filt[c * 16 + k];
        float bias = la_bias[c];

        float s = 0.0f, ss = 0.0f;
        float* hprow = &g_hp[(b * NC + c) * LP];

        #pragma unroll 1
        for (int i = 0; i < 9; i++) {
            int base = 4 * lane + 128 * i;
            if (base > 1040) continue;
            float win[20];
            #pragma unroll
            for (int j = 0; j < 5; j++) {
                float4 q = *reinterpret_cast<const float4*>(&sxp[base + 4 * j]);
                win[4 * j + 0] = q.x; win[4 * j + 1] = q.y;
                win[4 * j + 2] = q.z; win[4 * j + 3] = q.w;
            }
            float r0 = bias, r1 = bias, r2 = bias, r3 = bias, r4 = bias;
            #pragma unroll
            for (int k = 0; k < 16; k++) {
                float fk = f[k];
                r0 = fmaf(win[k    ], fk, r0);
                r1 = fmaf(win[k + 1], fk, r1);
                r2 = fmaf(win[k + 2], fk, r2);
                r3 = fmaf(win[k + 3], fk, r3);
                r4 = fmaf(win[k + 4], fk, r4);
            }
            if (base + 0 <= 1040) { s += r0; ss = fmaf(r0, r0, ss); }
            if (base + 1 <= 1040) { s += r1; ss = fmaf(r1, r1, ss); }
            if (base + 2 <= 1040) { s += r2; ss = fmaf(r2, r2, ss); }
            if (base + 3 <= 1040) { s += r3; ss = fmaf(r3, r3, ss); }
            int m0 = base >> 1;
            if (m0 <= 518) {
                float2 pv;
                pv.x = (r0 + r1 + r2) * (1.0f / 3.0f);
                pv.y = (r2 + r3 + r4) * (1.0f / 3.0f);
                *reinterpret_cast<float2*>(&hprow[m0]) = pv;
            }
        }
        #pragma unroll
        for (int o = 16; o > 0; o >>= 1) {
            s  += __shfl_down_sync(0xffffffffu, s,  o);
            ss += __shfl_down_sync(0xffffffffu, ss, o);
        }
        if (lane == 0) {
            atomicAdd(&g_st1[c],      (double)s);
            atomicAdd(&g_st1[NC + c], (double)ss);
        }
    }
}

// ---------------------------------------------------------------------------
// K3: both branches. BN1 folded into layer-1 weights (computed inline from
// stats), cp.async double-buffered prefetch of next channel's g_hp row.
// ---------------------------------------------------------------------------
__global__ __launch_bounds__(256) void k_branch(
    const float* __restrict__ bn1_g, const float* __restrict__ bn1_b,
    const float* __restrict__ a1_w, const float* __restrict__ a1_b,
    const float* __restrict__ e1_w, const float* __restrict__ e1_b,
    const float* __restrict__ f1_w, const float* __restrict__ f1_b,
    const float* __restrict__ fa_w, const float* __restrict__ fa_b) {

    __shared__ float sh[8][1328];

    int b = blockIdx.x;
    int t = threadIdx.x;
    int w = t >> 5, lane = t & 31;

    unsigned sbase = (unsigned)__cvta_generic_to_shared(&sh[0][0]);
    unsigned in_u32[2] = { sbase + (unsigned)(w * 1328) * 4u,
                           sbase + (unsigned)(w * 1328 + 528) * 4u };
    const float* inptr[2] = { &sh[w][0], &sh[w][528] };
    float* s1 = &sh[w][1056];

    int cbase = w * 4;

    {
        const float* src = &g_hp[(b * NC + cbase) * LP];
        #pragma unroll
        for (int i = 0; i < 5; i++) {
            int idx = lane + 32 * i;
            if (idx < 130)
                asm volatile("cp.async.ca.shared.global [%0], [%1], 16;"
                             :: "r"(in_u32[0] + idx * 16), "l"(src + idx * 4));
        }
        asm volatile("cp.async.commit_group;" ::: "memory");
    }

    #pragma unroll
    for (int cc = 0; cc < 4; cc++) {
        int c = cbase + cc;
        if (cc < 3) {
            const float* src = &g_hp[(b * NC + c + 1) * LP];
            unsigned dst = in_u32[(cc + 1) & 1];
            #pragma unroll
            for (int i = 0; i < 5; i++) {
                int idx = lane + 32 * i;
                if (idx < 130)
                    asm volatile("cp.async.ca.shared.global [%0], [%1], 16;"
                                 :: "r"(dst + idx * 16), "l"(src + idx * 4));
            }
            asm volatile("cp.async.commit_group;" ::: "memory");
            asm volatile("cp.async.wait_group 1;" ::: "memory");
        } else {
            asm volatile("cp.async.wait_group 0;" ::: "memory");
        }
        __syncwarp();
        const float* in = inptr[cc & 1];

        double Nn = (double)NB * (double)LRAW;
        double m = g_st1[c] / Nn;
        double var = g_st1[NC + c] / Nn - m * m;
        float sc = bn1_g[c] * rsqrtf((float)var + 1e-5f);
        float sf = bn1_b[c] - (float)m * sc;

        #pragma unroll 1
        for (int br = 0; br < 2; br++) {
            float w1r[8], acc1;
            {
                const float* wsrc = (br == 0) ? &a1_w[c * 8] : &f1_w[c * 8];
                float sum = 0.0f;
                #pragma unroll
                for (int j = 0; j < 8; j++) { w1r[j] = wsrc[j]; sum += w1r[j]; }
                float base = (br == 0) ? (a1_b[c] - sum) : (1.0f - f1_b[c]);
                acc1 = base + sf * sum;
                #pragma unroll
                for (int j = 0; j < 8; j++) w1r[j] *= sc;
            }

            #pragma unroll
            for (int i = 0; i < 2; i++) {
                int n0 = 4 * lane + 128 * i;
                int base = 2 * n0;
                float win[16];
                #pragma unroll
                for (int j = 0; j < 4; j++) {
                    float4 q = *reinterpret_cast<const float4*>(&in[base + 4 * j]);
                    win[4 * j + 0] = q.x; win[4 * j + 1] = q.y;
                    win[4 * j + 2] = q.z; win[4 * j + 3] = q.w;
                }
                float r0 = acc1, r1 = acc1, r2 = acc1, r3 = acc1;
                #pragma unroll
                for (int k = 0; k < 8; k++) {
                    float wk = w1r[k];
                    r0 = fmaf(win[k    ], wk, r0);
                    r1 = fmaf(win[k + 2], wk, r1);
                    r2 = fmaf(win[k + 4], wk, r2);
                    r3 = fmaf(win[k + 6], wk, r3);
                }
                float4 o;
                o.x = fmaxf(r0, 0.0f); o.y = fmaxf(r1, 0.0f);
                o.z = fmaxf(r2, 0.0f); o.w = fmaxf(r3, 0.0f);
                *reinterpret_cast<float4*>(&s1[n0]) = o;
            }
            __syncwarp();

            float w2r[8], acc2;
            if (br == 0) {
                #pragma unroll
                for (int j = 0; j < 8; j++) w2r[j] = e1_w[c * 8 + j];
                acc2 = 1.0f - e1_b[c];
            } else {
                float sum = 0.0f;
                #pragma unroll
                for (int j = 0; j < 8; j++) { w2r[j] = fa_w[c * 8 + j]; sum += w2r[j]; }
                acc2 = fa_b[c] - sum;
            }

            {
                int base = 8 * lane;
                float win[16];
                #pragma unroll
                for (int j = 0; j < 4; j++) {
                    float4 q = *reinterpret_cast<const float4*>(&s1[base + 4 * j]);
                    win[4 * j + 0] = q.x; win[4 * j + 1] = q.y;
                    win[4 * j + 2] = q.z; win[4 * j + 3] = q.w;
                }
                float r0 = acc2, r1 = acc2, r2 = acc2, r3 = acc2;
                #pragma unroll
                for (int k = 0; k < 8; k++) {
                    float wk = w2r[k];
                    r0 = fmaf(win[k    ], wk, r0);
                    r1 = fmaf(win[k + 2], wk, r1);
                    r2 = fmaf(win[k + 4], wk, r2);
                    r3 = fmaf(win[k + 6], wk, r3);
                }
                r0 = fmaxf(r0, 0.0f); r1 = fmaxf(r1, 0.0f);
                r2 = fmaxf(r2, 0.0f); r3 = fmaxf(r3, 0.0f);
                float y = fmaxf(fmaxf(r0, r1), fmaxf(r2, r3));
                float s = 0.0f, ss = 0.0f;
                if (lane < L3) {
                    if (br == 0) g_y1[(b * NC + c) * L3 + lane] = y;
                    else         g_y2[(b * NC + c) * L3 + lane] = y;
                    s = y; ss = y * y;
                }
                #pragma unroll
                for (int o = 16; o > 0; o >>= 1) {
                    s  += __shfl_down_sync(0xffffffffu, s,  o);
                    ss += __shfl_down_sync(0xffffffffu, ss, o);
                }
                if (lane == 0) {
                    double* st = (br == 0) ? g_st2 : g_st3;
                    atomicAdd(&st[c],      (double)s);
                    atomicAdd(&st[NC + c], (double)ss);
                }
            }
            __syncwarp();
        }
    }
}

// ---------------------------------------------------------------------------
// K5: BN2/BN3 (inline from stats) + final Eventually -> z (B,768)
// ---------------------------------------------------------------------------
__global__ __launch_bounds__(256) void k_zassm(
    const float* __restrict__ e2_w, const float* __restrict__ e2_b,
    const float* __restrict__ f2_w, const float* __restrict__ f2_b,
    const float* __restrict__ bn2_g, const float* __restrict__ bn2_b,
    const float* __restrict__ bn3_g, const float* __restrict__ bn3_b) {
    __shared__ float ssc[2][NC], ssh[2][NC];
    int b = blockIdx.x;
    int t = threadIdx.x;
    if (t < 64) {
        int br = t >> 5, c = t & 31;
        const double* st = br ? g_st3 : g_st2;
        float gam = br ? bn3_g[c] : bn2_g[c];
        float bet = br ? bn3_b[c] : bn2_b[c];
        double Nn = (double)NB * (double)L3;
        double m = st[c] / Nn;
        double v = st[NC + c] / Nn - m * m;
        float sc = gam * rsqrtf((float)v + 1e-5f);
        ssc[br][c] = sc;
        ssh[br][c] = bet - (float)m * sc;
    }
    __syncthreads();

    for (int o = t; o < ZDIM; o += 256) {
        int br  = o / 384;
        int rem = o - br * 384;
        int c = rem / L4, n = rem - c * L4;
        const float* y  = br ? &g_y2[(b * NC + c) * L3] : &g_y1[(b * NC + c) * L3];
        const float* wv = br ? &f2_w[c * 8] : &e2_w[c * 8];
        float bb = br ? f2_b[c] : e2_b[c];
        float scv = ssc[br][c], shv = ssh[br][c];
        float acc = 1.0f - bb;
        #pragma unroll
        for (int j = 0; j < 8; j++)
            acc = fmaf(fmaf(y[2 * n + j], scv, shv), wv[j], acc);
        g_z[b * ZDIM + o] = fmaxf(acc, 0.0f);
    }
}

// ---------------------------------------------------------------------------
// GEMM A (high-intensity): BM=128, BN=64, BK=16, 256 threads, 8x4 micro-tile.
// C = relu(A[MxK] @ W[KxN] + bias). Register prefetch of next K-tile.
// ---------------------------------------------------------------------------
__global__ __launch_bounds__(256) void k_gemm_relu_128(
    const float* __restrict__ A, const float* __restrict__ W,
    const float* __restrict__ bias, float* __restrict__ Cc,
    int M, int N, int K) {
    __shared__ float As[16][132];   // [k][m], padded
    __shared__ float Ws[16][64];    // [k][n]

    int tid = threadIdx.x;
    int tx = tid & 15, ty = tid >> 4;
    int rowBase = blockIdx.y * 128;
    int colBase = blockIdx.x * 64;

    // A loaders: 2 float4 per thread (128x16 = 512 float4)
    int aRow[2], aC4[2];
    const float* Ap[2];
    #pragma unroll
    for (int i = 0; i < 2; i++) {
        int idx = tid + i * 256;
        aRow[i] = idx >> 2;
        aC4[i]  = (idx & 3) * 4;
        Ap[i] = A + (rowBase + aRow[i]) * K + aC4[i];
    }
    // W loader: 1 float4 per thread (16x64 = 256 float4)
    int wRow = tid >> 4, wCol = (tid & 15) * 4;
    const float* Wp = W + wRow * N + colBase + wCol;

    float4 avr[2], wvr;
    #pragma unroll
    for (int i = 0; i < 2; i++) avr[i] = *reinterpret_cast<const float4*>(Ap[i]);
    wvr = *reinterpret_cast<const float4*>(Wp);

    float acc[8][4] = {};

    for (int kt = 0; kt < K; kt += 16) {
        __syncthreads();
        #pragma unroll
        for (int i = 0; i < 2; i++) {
            As[aC4[i] + 0][aRow[i]] = avr[i].x;
            As[aC4[i] + 1][aRow[i]] = avr[i].y;
            As[aC4[i] + 2][aRow[i]] = avr[i].z;
            As[aC4[i] + 3][aRow[i]] = avr[i].w;
        }
        *reinterpret_cast<float4*>(&Ws[wRow][wCol]) = wvr;
        __syncthreads();
        if (kt + 16 < K) {
            #pragma unroll
            for (int i = 0; i < 2; i++)
                avr[i] = *reinterpret_cast<const float4*>(Ap[i] + kt + 16);
            wvr = *reinterpret_cast<const float4*>(Wp + (kt + 16) * N);
        }
        #pragma unroll
        for (int k = 0; k < 16; k++) {
            float4 a0 = *reinterpret_cast<const float4*>(&As[k][ty * 8]);
            float4 a1 = *reinterpret_cast<const float4*>(&As[k][ty * 8 + 4]);
            float4 wv = *reinterpret_cast<const float4*>(&Ws[k][tx * 4]);
            float aa[8] = { a0.x, a0.y, a0.z, a0.w, a1.x, a1.y, a1.z, a1.w };
            float wb[4] = { wv.x, wv.y, wv.z, wv.w };
            #pragma unroll
            for (int i = 0; i < 8; i++)
                #pragma unroll
                for (int j = 0; j < 4; j++)
                    acc[i][j] = fmaf(aa[i], wb[j], acc[i][j]);
        }
    }

    float4 bv = *reinterpret_cast<const float4*>(&bias[colBase + tx * 4]);
    float bj[4] = { bv.x, bv.y, bv.z, bv.w };
    #pragma unroll
    for (int i = 0; i < 8; i++) {
        int r = rowBase + ty * 8 + i;
        float4 o;
        o.x = fmaxf(acc[i][0] + bj[0], 0.0f);
        o.y = fmaxf(acc[i][1] + bj[1], 0.0f);
        o.z = fmaxf(acc[i][2] + bj[2], 0.0f);
        o.w = fmaxf(acc[i][3] + bj[3], 0.0f);
        *reinterpret_cast<float4*>(&Cc[r * N + colBase + tx * 4]) = o;
    }
}

// ---------------------------------------------------------------------------
// GEMM B (round-7 proven): BM=BN=64, BK=16, 256 threads, 4x4 micro-tile.
// ---------------------------------------------------------------------------
__global__ __launch_bounds__(256) void k_gemm_relu(
    const float* __restrict__ A, const float* __restrict__ W,
    const float* __restrict__ bias, float* __restrict__ Cc,
    int M, int N, int K) {
    __shared__ float As[16][68];
    __shared__ float Ws[16][64];

    int tid = threadIdx.x;
    int tx = tid & 15, ty = tid >> 4;
    int rowBase = blockIdx.y * 64;
    int colBase = blockIdx.x * 64;

    int aRow = tid >> 2, aCol = (tid & 3) * 4;
    int wRow = tid >> 4, wCol = (tid & 15) * 4;

    const float* Aptr = A + (rowBase + aRow) * K + aCol;
    const float* Wptr = W + wRow * N + colBase + wCol;

    float4 av = *reinterpret_cast<const float4*>(Aptr);
    float4 wv = *reinterpret_cast<const float4*>(Wptr);

    float acc[4][4] = {};

    for (int kt = 0; kt < K; kt += 16) {
        __syncthreads();
        As[aCol + 0][aRow] = av.x;
        As[aCol + 1][aRow] = av.y;
        As[aCol + 2][aRow] = av.z;
        As[aCol + 3][aRow] = av.w;
        *reinterpret_cast<float4*>(&Ws[wRow][wCol]) = wv;
        __syncthreads();
        if (kt + 16 < K) {
            av = *reinterpret_cast<const float4*>(Aptr + kt + 16);
            wv = *reinterpret_cast<const float4*>(Wptr + (kt + 16) * N);
        }
        #pragma unroll
        for (int k = 0; k < 16; k++) {
            float4 a = *reinterpret_cast<const float4*>(&As[k][ty * 4]);
            float4 ww = *reinterpret_cast<const float4*>(&Ws[k][tx * 4]);
            float aa[4] = { a.x, a.y, a.z, a.w };
            float wb[4] = { ww.x, ww.y, ww.z, ww.w };
            #pragma unroll
            for (int i = 0; i < 4; i++)
                #pragma unroll
                for (int j = 0; j < 4; j++)
                    acc[i][j] = fmaf(aa[i], wb[j], acc[i][j]);
        }
    }

    float4 bv = *reinterpret_cast<const float4*>(&bias[colBase + tx * 4]);
    float bj[4] = { bv.x, bv.y, bv.z, bv.w };
    #pragma unroll
    for (int i = 0; i < 4; i++) {
        int r = rowBase + ty * 4 + i;
        float4 o;
        o.x = fmaxf(acc[i][0] + bj[0], 0.0f);
        o.y = fmaxf(acc[i][1] + bj[1], 0.0f);
        o.z = fmaxf(acc[i][2] + bj[2], 0.0f);
        o.w = fmaxf(acc[i][3] + bj[3], 0.0f);
        *reinterpret_cast<float4*>(&Cc[r * N + colBase + tx * 4]) = o;
    }
}

// ---------------------------------------------------------------------------
// Final FC: (B,128) @ (128,10) + bias, relu. One warp per batch row.
// ---------------------------------------------------------------------------
__global__ __launch_bounds__(256) void k_fc4(const float* __restrict__ w4,
                                             const float* __restrict__ b4,
                                             float* __restrict__ out) {
    int b = blockIdx.x * 8 + (threadIdx.x >> 5);
    int lane = threadIdx.x & 31;
    const float* row = &g_c3[b * 128];
    float v0 = row[lane], v1 = row[lane + 32], v2 = row[lane + 64], v3 = row[lane + 96];
    for (int j = 0; j < 10; j++) {
        float p = v0 * w4[lane * 10 + j]
                + v1 * w4[(lane + 32) * 10 + j]
                + v2 * w4[(lane + 64) * 10 + j]
                + v3 * w4[(lane + 96) * 10 + j];
        #pragma unroll
        for (int o = 16; o > 0; o >>= 1) p += __shfl_down_sync(0xffffffffu, p, o);
        if (lane == 0) out[b * 10 + j] = fmaxf(p + b4[j], 0.0f);
    }
}

// ---------------------------------------------------------------------------
// Launch
// ---------------------------------------------------------------------------
extern "C" void kernel_launch(void* const* d_in, const int* in_sizes, int n_in,
                              void* d_out, int out_size) {
    const float* x       = (const float*)d_in[0];
    const float* la_a    = (const float*)d_in[1];
    const float* la_b    = (const float*)d_in[2];
    const float* la_bias = (const float*)d_in[3];
    const float* bn1_g   = (const float*)d_in[4];
    const float* bn1_b   = (const float*)d_in[5];
    const float* a1_w    = (const float*)d_in[6];
    const float* a1_b    = (const float*)d_in[7];
    const float* e1_w    = (const float*)d_in[8];
    const float* e1_b    = (const float*)d_in[9];
    const float* bn2_g   = (const float*)d_in[10];
    const float* bn2_b   = (const float*)d_in[11];
    const float* e2_w    = (const float*)d_in[12];
    const float* e2_b    = (const float*)d_in[13];
    const float* f1_w    = (const float*)d_in[14];
    const float* f1_b    = (const float*)d_in[15];
    const float* fa_w    = (const float*)d_in[16];
    const float* fa_b    = (const float*)d_in[17];
    const float* bn3_g   = (const float*)d_in[18];
    const float* bn3_b   = (const float*)d_in[19];
    const float* f2_w    = (const float*)d_in[20];
    const float* f2_b    = (const float*)d_in[21];
    const float* w1      = (const float*)d_in[22];
    const float* b1      = (const float*)d_in[23];
    const float* w2      = (const float*)d_in[24];
    const float* b2      = (const float*)d_in[25];
    const float* w3      = (const float*)d_in[26];
    const float* b3      = (const float*)d_in[27];
    const float* w4      = (const float*)d_in[28];
    const float* b4      = (const float*)d_in[29];
    float* out = (float*)d_out;

    float *p_z = nullptr, *p_c1 = nullptr, *p_c2 = nullptr, *p_c3 = nullptr;
    cudaGetSymbolAddress((void**)&p_z,  g_z);
    cudaGetSymbolAddress((void**)&p_c1, g_c1);
    cudaGetSymbolAddress((void**)&p_c2, g_c2);
    cudaGetSymbolAddress((void**)&p_c3, g_c3);

    k_init<<<1, 512>>>(la_a, la_b);
    k_conv<<<NB, 256>>>(x, la_bias);
    k_branch<<<NB, 256>>>(bn1_g, bn1_b, a1_w, a1_b, e1_w, e1_b,
                          f1_w, f1_b, fa_w, fa_b);
    k_zassm<<<NB, 256>>>(e2_w, e2_b, f2_w, f2_b, bn2_g, bn2_b, bn3_g, bn3_b);

    {   // 1024x1024x768 : 128-row tiles -> 16x8 = 128 CTAs (~1 wave)
        dim3 g(1024 / 64, NB / 128);
        k_gemm_relu_128<<<g, 256>>>(p_z, w1, b1, p_c1, NB, 1024, 768);
    }
    {   // 1024x512x1024 : 64x64 tiles -> 8x16 = 128 CTAs
        dim3 g(512 / 64, NB / 64);
        k_gemm_relu<<<g, 256>>>(p_c1, w2, b2, p_c2, NB, 512, 1024);
    }
    {   // 1024x128x512 : 2x16 = 32 CTAs
        dim3 g(128 / 64, NB / 64);
        k_gemm_relu<<<g, 256>>>(p_c2, w3, b3, p_c3, NB, 128, 512);
    }
    k_fc4<<<NB / 8, 256>>>(w4, b4, out);
}

// round 11
// speedup vs baseline: 1.3986x; 1.0613x over previous
#include <cuda_runtime.h>
#include <math.h>

// ---------------------------------------------------------------------------
// Problem constants
// ---------------------------------------------------------------------------
#define NB   1024
#define NC   32
#define LIN  1024
#define LRAW 1041
#define LP   520
#define L1   257
#define L2   125
#define L3   31
#define L4   12
#define ZDIM 768

// ---------------------------------------------------------------------------
// Scratch
// ---------------------------------------------------------------------------
__device__ float  g_filt[NC * 16];
__device__ float  g_hp[NB * NC * LP];
__device__ double g_st1[2 * NC];
__device__ double g_st2[2 * NC];
__device__ double g_st3[2 * NC];
__device__ float  g_y1[NB * NC * L3];
__device__ float  g_y2[NB * NC * L3];
__device__ float  g_z [NB * ZDIM];
__device__ float  g_c1[NB * 1024];
__device__ float  g_c2[NB * 512];
__device__ float  g_c3[NB * 128];

// packed f32x2 FMA: d.lo += a.lo*b.lo ; d.hi += a.hi*b.hi
#define FFMA2(d, a, b) \
    asm volatile("fma.rn.f32x2 %0, %1, %2, %0;" : "+l"(d) : "l"(a), "l"(b))

// broadcast-pack one float into both halves of a u64
__device__ __forceinline__ unsigned long long packdup(float v) {
    unsigned long long p;
    asm("mov.b64 %0, {%1, %1};" : "=l"(p) : "r"(__float_as_uint(v)));
    return p;
}

// ---------------------------------------------------------------------------
// K0: zero stats + build Laplace filter bank
// ---------------------------------------------------------------------------
__global__ void k_init(const float* __restrict__ la_a, const float* __restrict__ la_b) {
    int t = threadIdx.x;
    if (t < 2 * NC) { g_st1[t] = 0.0; g_st2[t] = 0.0; g_st3[t] = 0.0; }
    if (t < NC * 16) {
        int c = t >> 4, k = t & 15;
        const double A = 0.08, ep = 0.03, tal = 0.1, f = 50.0;
        const double w = 2.0 * 3.14159265358979323846 * f;
        const double q = 1.0 - ep * ep;
        double tk = (double)k / 15.0;
        double p  = tk - (double)la_b[c] / (double)la_a[c];
        double arg = w * (p - tal);
        double y = A * exp(-ep / sqrt(q) * arg) * (-sin(arg));
        g_filt[t] = (float)y;
    }
}

// ---------------------------------------------------------------------------
// K1: conv (pad 16/16) + la_bias + BN1 stats + avgpool(3,2)  -> g_hp
// ---------------------------------------------------------------------------
__global__ __launch_bounds__(256) void k_conv(const float* __restrict__ x,
                                              const float* __restrict__ la_bias) {
    __shared__ float sxp[1060];

    int b = blockIdx.x;
    int t = threadIdx.x;

    for (int i = t; i < 1060; i += 256) {
        int xi = i - 16;
        sxp[i] = (xi >= 0 && xi < LIN) ? x[b * LIN + xi] : 0.0f;
    }
    __syncthreads();

    int w = t >> 5, lane = t & 31;

    #pragma unroll 1
    for (int cc = 0; cc < 4; cc++) {
        int c = w * 4 + cc;
        float f[16];
        #pragma unroll
        for (int k = 0; k < 16; k++) f[k] = g_filt[c * 16 + k];
        float bias = la_bias[c];

        float s = 0.0f, ss = 0.0f;
        float* hprow = &g_hp[(b * NC + c) * LP];

        #pragma unroll 1
        for (int i = 0; i < 9; i++) {
            int base = 4 * lane + 128 * i;
            if (base > 1040) continue;
            float win[20];
            #pragma unroll
            for (int j = 0; j < 5; j++) {
                float4 q = *reinterpret_cast<const float4*>(&sxp[base + 4 * j]);
                win[4 * j + 0] = q.x; win[4 * j + 1] = q.y;
                win[4 * j + 2] = q.z; win[4 * j + 3] = q.w;
            }
            float r0 = bias, r1 = bias, r2 = bias, r3 = bias, r4 = bias;
            #pragma unroll
            for (int k = 0; k < 16; k++) {
                float fk = f[k];
                r0 = fmaf(win[k    ], fk, r0);
                r1 = fmaf(win[k + 1], fk, r1);
                r2 = fmaf(win[k + 2], fk, r2);
                r3 = fmaf(win[k + 3], fk, r3);
                r4 = fmaf(win[k + 4], fk, r4);
            }
            if (base + 0 <= 1040) { s += r0; ss = fmaf(r0, r0, ss); }
            if (base + 1 <= 1040) { s += r1; ss = fmaf(r1, r1, ss); }
            if (base + 2 <= 1040) { s += r2; ss = fmaf(r2, r2, ss); }
            if (base + 3 <= 1040) { s += r3; ss = fmaf(r3, r3, ss); }
            int m0 = base >> 1;
            if (m0 <= 518) {
                float2 pv;
                pv.x = (r0 + r1 + r2) * (1.0f / 3.0f);
                pv.y = (r2 + r3 + r4) * (1.0f / 3.0f);
                *reinterpret_cast<float2*>(&hprow[m0]) = pv;
            }
        }
        #pragma unroll
        for (int o = 16; o > 0; o >>= 1) {
            s  += __shfl_down_sync(0xffffffffu, s,  o);
            ss += __shfl_down_sync(0xffffffffu, ss, o);
        }
        if (lane == 0) {
            atomicAdd(&g_st1[c],      (double)s);
            atomicAdd(&g_st1[NC + c], (double)ss);
        }
    }
}

// ---------------------------------------------------------------------------
// K3: both branches. BN1 folded into layer-1 weights, cp.async prefetch.
// ---------------------------------------------------------------------------
__global__ __launch_bounds__(256) void k_branch(
    const float* __restrict__ bn1_g, const float* __restrict__ bn1_b,
    const float* __restrict__ a1_w, const float* __restrict__ a1_b,
    const float* __restrict__ e1_w, const float* __restrict__ e1_b,
    const float* __restrict__ f1_w, const float* __restrict__ f1_b,
    const float* __restrict__ fa_w, const float* __restrict__ fa_b) {

    __shared__ float sh[8][1328];

    int b = blockIdx.x;
    int t = threadIdx.x;
    int w = t >> 5, lane = t & 31;

    unsigned sbase = (unsigned)__cvta_generic_to_shared(&sh[0][0]);
    unsigned in_u32[2] = { sbase + (unsigned)(w * 1328) * 4u,
                           sbase + (unsigned)(w * 1328 + 528) * 4u };
    const float* inptr[2] = { &sh[w][0], &sh[w][528] };
    float* s1 = &sh[w][1056];

    int cbase = w * 4;

    {
        const float* src = &g_hp[(b * NC + cbase) * LP];
        #pragma unroll
        for (int i = 0; i < 5; i++) {
            int idx = lane + 32 * i;
            if (idx < 130)
                asm volatile("cp.async.ca.shared.global [%0], [%1], 16;"
                             :: "r"(in_u32[0] + idx * 16), "l"(src + idx * 4));
        }
        asm volatile("cp.async.commit_group;" ::: "memory");
    }

    #pragma unroll
    for (int cc = 0; cc < 4; cc++) {
        int c = cbase + cc;
        if (cc < 3) {
            const float* src = &g_hp[(b * NC + c + 1) * LP];
            unsigned dst = in_u32[(cc + 1) & 1];
            #pragma unroll
            for (int i = 0; i < 5; i++) {
                int idx = lane + 32 * i;
                if (idx < 130)
                    asm volatile("cp.async.ca.shared.global [%0], [%1], 16;"
                                 :: "r"(dst + idx * 16), "l"(src + idx * 4));
            }
            asm volatile("cp.async.commit_group;" ::: "memory");
            asm volatile("cp.async.wait_group 1;" ::: "memory");
        } else {
            asm volatile("cp.async.wait_group 0;" ::: "memory");
        }
        __syncwarp();
        const float* in = inptr[cc & 1];

        double Nn = (double)NB * (double)LRAW;
        double m = g_st1[c] / Nn;
        double var = g_st1[NC + c] / Nn - m * m;
        float sc = bn1_g[c] * rsqrtf((float)var + 1e-5f);
        float sf = bn1_b[c] - (float)m * sc;

        #pragma unroll 1
        for (int br = 0; br < 2; br++) {
            float w1r[8], acc1;
            {
                const float* wsrc = (br == 0) ? &a1_w[c * 8] : &f1_w[c * 8];
                float sum = 0.0f;
                #pragma unroll
                for (int j = 0; j < 8; j++) { w1r[j] = wsrc[j]; sum += w1r[j]; }
                float base = (br == 0) ? (a1_b[c] - sum) : (1.0f - f1_b[c]);
                acc1 = base + sf * sum;
                #pragma unroll
                for (int j = 0; j < 8; j++) w1r[j] *= sc;
            }

            #pragma unroll
            for (int i = 0; i < 2; i++) {
                int n0 = 4 * lane + 128 * i;
                int base = 2 * n0;
                float win[16];
                #pragma unroll
                for (int j = 0; j < 4; j++) {
                    float4 q = *reinterpret_cast<const float4*>(&in[base + 4 * j]);
                    win[4 * j + 0] = q.x; win[4 * j + 1] = q.y;
                    win[4 * j + 2] = q.z; win[4 * j + 3] = q.w;
                }
                float r0 = acc1, r1 = acc1, r2 = acc1, r3 = acc1;
                #pragma unroll
                for (int k = 0; k < 8; k++) {
                    float wk = w1r[k];
                    r0 = fmaf(win[k    ], wk, r0);
                    r1 = fmaf(win[k + 2], wk, r1);
                    r2 = fmaf(win[k + 4], wk, r2);
                    r3 = fmaf(win[k + 6], wk, r3);
                }
                float4 o;
                o.x = fmaxf(r0, 0.0f); o.y = fmaxf(r1, 0.0f);
                o.z = fmaxf(r2, 0.0f); o.w = fmaxf(r3, 0.0f);
                *reinterpret_cast<float4*>(&s1[n0]) = o;
            }
            __syncwarp();

            float w2r[8], acc2;
            if (br == 0) {
                #pragma unroll
                for (int j = 0; j < 8; j++) w2r[j] = e1_w[c * 8 + j];
                acc2 = 1.0f - e1_b[c];
            } else {
                float sum = 0.0f;
                #pragma unroll
                for (int j = 0; j < 8; j++) { w2r[j] = fa_w[c * 8 + j]; sum += w2r[j]; }
                acc2 = fa_b[c] - sum;
            }

            {
                int base = 8 * lane;
                float win[16];
                #pragma unroll
                for (int j = 0; j < 4; j++) {
                    float4 q = *reinterpret_cast<const float4*>(&s1[base + 4 * j]);
                    win[4 * j + 0] = q.x; win[4 * j + 1] = q.y;
                    win[4 * j + 2] = q.z; win[4 * j + 3] = q.w;
                }
                float r0 = acc2, r1 = acc2, r2 = acc2, r3 = acc2;
                #pragma unroll
                for (int k = 0; k < 8; k++) {
                    float wk = w2r[k];
                    r0 = fmaf(win[k    ], wk, r0);
                    r1 = fmaf(win[k + 2], wk, r1);
                    r2 = fmaf(win[k + 4], wk, r2);
                    r3 = fmaf(win[k + 6], wk, r3);
                }
                r0 = fmaxf(r0, 0.0f); r1 = fmaxf(r1, 0.0f);
                r2 = fmaxf(r2, 0.0f); r3 = fmaxf(r3, 0.0f);
                float y = fmaxf(fmaxf(r0, r1), fmaxf(r2, r3));
                float s = 0.0f, ss = 0.0f;
                if (lane < L3) {
                    if (br == 0) g_y1[(b * NC + c) * L3 + lane] = y;
                    else         g_y2[(b * NC + c) * L3 + lane] = y;
                    s = y; ss = y * y;
                }
                #pragma unroll
                for (int o = 16; o > 0; o >>= 1) {
                    s  += __shfl_down_sync(0xffffffffu, s,  o);
                    ss += __shfl_down_sync(0xffffffffu, ss, o);
                }
                if (lane == 0) {
                    double* st = (br == 0) ? g_st2 : g_st3;
                    atomicAdd(&st[c],      (double)s);
                    atomicAdd(&st[NC + c], (double)ss);
                }
            }
            __syncwarp();
        }
    }
}

// ---------------------------------------------------------------------------
// K5: BN2/BN3 (inline from stats) + final Eventually -> z (B,768)
// ---------------------------------------------------------------------------
__global__ __launch_bounds__(256) void k_zassm(
    const float* __restrict__ e2_w, const float* __restrict__ e2_b,
    const float* __restrict__ f2_w, const float* __restrict__ f2_b,
    const float* __restrict__ bn2_g, const float* __restrict__ bn2_b,
    const float* __restrict__ bn3_g, const float* __restrict__ bn3_b) {
    __shared__ float ssc[2][NC], ssh[2][NC];
    int b = blockIdx.x;
    int t = threadIdx.x;
    if (t < 64) {
        int br = t >> 5, c = t & 31;
        const double* st = br ? g_st3 : g_st2;
        float gam = br ? bn3_g[c] : bn2_g[c];
        float bet = br ? bn3_b[c] : bn2_b[c];
        double Nn = (double)NB * (double)L3;
        double m = st[c] / Nn;
        double v = st[NC + c] / Nn - m * m;
        float sc = gam * rsqrtf((float)v + 1e-5f);
        ssc[br][c] = sc;
        ssh[br][c] = bet - (float)m * sc;
    }
    __syncthreads();

    for (int o = t; o < ZDIM; o += 256) {
        int br  = o / 384;
        int rem = o - br * 384;
        int c = rem / L4, n = rem - c * L4;
        const float* y  = br ? &g_y2[(b * NC + c) * L3] : &g_y1[(b * NC + c) * L3];
        const float* wv = br ? &f2_w[c * 8] : &e2_w[c * 8];
        float bb = br ? f2_b[c] : e2_b[c];
        float scv = ssc[br][c], shv = ssh[br][c];
        float acc = 1.0f - bb;
        #pragma unroll
        for (int j = 0; j < 8; j++)
            acc = fmaf(fmaf(y[2 * n + j], scv, shv), wv[j], acc);
        g_z[b * ZDIM + o] = fmaxf(acc, 0.0f);
    }
}

// ---------------------------------------------------------------------------
// FFMA2 GEMM: C = relu(A[MxK] @ W[KxN] + bias). BN=64, BK=16, 256 threads.
// Micro-tile: R=BM/16 rows (R/2 packed M-pairs) x 4 cols. W smem NOT
// duplicated; broadcast pairs {w,w} built in registers (1 mov.b64 each).
// Crossbar traffic: 1.5 B/FMA (BM=128) -> FFMA2-pipe bound, not LDS bound.
// ---------------------------------------------------------------------------
template<int BM>
__global__ __launch_bounds__(256) void k_gemm_relu_x2(
    const float* __restrict__ A, const float* __restrict__ W,
    const float* __restrict__ bias, float* __restrict__ Cc,
    int M, int N, int K) {
    constexpr int R = BM / 16;        // rows per thread (8 or 4)
    constexpr int P = R / 2;          // packed M-pairs (4 or 2)
    constexpr int ALOADS = BM / 64;   // float4 of A per thread per tile (2 or 1)
    __shared__ float As[16][BM + 4];  // [k][m] transposed; row base 16B-aligned
    __shared__ float Ws[16][64];      // [k][n]

    int tid = threadIdx.x;
    int tx = tid & 15, ty = tid >> 4;
    int rowBase = blockIdx.y * BM;
    int colBase = blockIdx.x * 64;

    int aRow[ALOADS], aC4[ALOADS];
    const float* Ap[ALOADS];
    #pragma unroll
    for (int i = 0; i < ALOADS; i++) {
        int idx = tid + i * 256;
        aRow[i] = idx >> 2;
        aC4[i]  = (idx & 3) * 4;
        Ap[i] = A + (rowBase + aRow[i]) * K + aC4[i];
    }
    int wRow = tid >> 4, wCol = (tid & 15) * 4;
    const float* Wp = W + wRow * N + colBase + wCol;

    float4 avr[ALOADS];
    #pragma unroll
    for (int i = 0; i < ALOADS; i++) avr[i] = *reinterpret_cast<const float4*>(Ap[i]);
    float4 wvr = *reinterpret_cast<const float4*>(Wp);

    unsigned long long acc[P][4];
    #pragma unroll
    for (int i = 0; i < P; i++)
        #pragma unroll
        for (int j = 0; j < 4; j++) acc[i][j] = 0ull;

    for (int kt = 0; kt < K; kt += 16) {
        __syncthreads();
        #pragma unroll
        for (int i = 0; i < ALOADS; i++) {
            As[aC4[i] + 0][aRow[i]] = avr[i].x;
            As[aC4[i] + 1][aRow[i]] = avr[i].y;
            As[aC4[i] + 2][aRow[i]] = avr[i].z;
            As[aC4[i] + 3][aRow[i]] = avr[i].w;
        }
        *reinterpret_cast<float4*>(&Ws[wRow][wCol]) = wvr;
        __syncthreads();
        if (kt + 16 < K) {
            #pragma unroll
            for (int i = 0; i < ALOADS; i++)
                avr[i] = *reinterpret_cast<const float4*>(Ap[i] + kt + 16);
            wvr = *reinterpret_cast<const float4*>(Wp + (kt + 16) * N);
        }
        #pragma unroll
        for (int k = 0; k < 16; k++) {
            // a pairs: R consecutive floats at 16B-aligned base -> ulonglong2 loads
            unsigned long long ap[P];
            #pragma unroll
            for (int i = 0; i < P; i += 2) {
                ulonglong2 q = *reinterpret_cast<const ulonglong2*>(&As[k][ty * R + 4 * (i >> 1)]);
                ap[i] = q.x;
                if (i + 1 < P) ap[i + 1] = q.y;
            }
            float4 wv = *reinterpret_cast<const float4*>(&Ws[k][tx * 4]);
            unsigned long long wp[4] = { packdup(wv.x), packdup(wv.y),
                                         packdup(wv.z), packdup(wv.w) };
            #pragma unroll
            for (int i = 0; i < P; i++)
                #pragma unroll
                for (int j = 0; j < 4; j++)
                    FFMA2(acc[i][j], ap[i], wp[j]);
        }
    }

    float4 bv = *reinterpret_cast<const float4*>(&bias[colBase + tx * 4]);
    float bj[4] = { bv.x, bv.y, bv.z, bv.w };
    #pragma unroll
    for (int i = 0; i < P; i++) {
        int r0 = rowBase + ty * R + 2 * i;
        float lo[4], hi[4];
        #pragma unroll
        for (int j = 0; j < 4; j++) {
            lo[j] = __uint_as_float((unsigned)(acc[i][j] & 0xffffffffull));
            hi[j] = __uint_as_float((unsigned)(acc[i][j] >> 32));
        }
        float4 o0, o1;
        o0.x = fmaxf(lo[0] + bj[0], 0.0f); o0.y = fmaxf(lo[1] + bj[1], 0.0f);
        o0.z = fmaxf(lo[2] + bj[2], 0.0f); o0.w = fmaxf(lo[3] + bj[3], 0.0f);
        o1.x = fmaxf(hi[0] + bj[0], 0.0f); o1.y = fmaxf(hi[1] + bj[1], 0.0f);
        o1.z = fmaxf(hi[2] + bj[2], 0.0f); o1.w = fmaxf(hi[3] + bj[3], 0.0f);
        *reinterpret_cast<float4*>(&Cc[r0 * N + colBase + tx * 4])       = o0;
        *reinterpret_cast<float4*>(&Cc[(r0 + 1) * N + colBase + tx * 4]) = o1;
    }
}

// ---------------------------------------------------------------------------
// Final FC: (B,128) @ (128,10) + bias, relu. One warp per batch row.
// ---------------------------------------------------------------------------
__global__ __launch_bounds__(256) void k_fc4(const float* __restrict__ w4,
                                             const float* __restrict__ b4,
                                             float* __restrict__ out) {
    int b = blockIdx.x * 8 + (threadIdx.x >> 5);
    int lane = threadIdx.x & 31;
    const float* row = &g_c3[b * 128];
    float v0 = row[lane], v1 = row[lane + 32], v2 = row[lane + 64], v3 = row[lane + 96];
    for (int j = 0; j < 10; j++) {
        float p = v0 * w4[lane * 10 + j]
                + v1 * w4[(lane + 32) * 10 + j]
                + v2 * w4[(lane + 64) * 10 + j]
                + v3 * w4[(lane + 96) * 10 + j];
        #pragma unroll
        for (int o = 16; o > 0; o >>= 1) p += __shfl_down_sync(0xffffffffu, p, o);
        if (lane == 0) out[b * 10 + j] = fmaxf(p + b4[j], 0.0f);
    }
}

// ---------------------------------------------------------------------------
// Launch
// ---------------------------------------------------------------------------
extern "C" void kernel_launch(void* const* d_in, const int* in_sizes, int n_in,
                              void* d_out, int out_size) {
    const float* x       = (const float*)d_in[0];
    const float* la_a    = (const float*)d_in[1];
    const float* la_b    = (const float*)d_in[2];
    const float* la_bias = (const float*)d_in[3];
    const float* bn1_g   = (const float*)d_in[4];
    const float* bn1_b   = (const float*)d_in[5];
    const float* a1_w    = (const float*)d_in[6];
    const float* a1_b    = (const float*)d_in[7];
    const float* e1_w    = (const float*)d_in[8];
    const float* e1_b    = (const float*)d_in[9];
    const float* bn2_g   = (const float*)d_in[10];
    const float* bn2_b   = (const float*)d_in[11];
    const float* e2_w    = (const float*)d_in[12];
    const float* e2_b    = (const float*)d_in[13];
    const float* f1_w    = (const float*)d_in[14];
    const float* f1_b    = (const float*)d_in[15];
    const float* fa_w    = (const float*)d_in[16];
    const float* fa_b    = (const float*)d_in[17];
    const float* bn3_g   = (const float*)d_in[18];
    const float* bn3_b   = (const float*)d_in[19];
    const float* f2_w    = (const float*)d_in[20];
    const float* f2_b    = (const float*)d_in[21];
    const float* w1      = (const float*)d_in[22];
    const float* b1      = (const float*)d_in[23];
    const float* w2      = (const float*)d_in[24];
    const float* b2      = (const float*)d_in[25];
    const float* w3      = (const float*)d_in[26];
    const float* b3      = (const float*)d_in[27];
    const float* w4      = (const float*)d_in[28];
    const float* b4      = (const float*)d_in[29];
    float* out = (float*)d_out;

    float *p_z = nullptr, *p_c1 = nullptr, *p_c2 = nullptr, *p_c3 = nullptr;
    cudaGetSymbolAddress((void**)&p_z,  g_z);
    cudaGetSymbolAddress((void**)&p_c1, g_c1);
    cudaGetSymbolAddress((void**)&p_c2, g_c2);
    cudaGetSymbolAddress((void**)&p_c3, g_c3);

    k_init<<<1, 512>>>(la_a, la_b);
    k_conv<<<NB, 256>>>(x, la_bias);
    k_branch<<<NB, 256>>>(bn1_g, bn1_b, a1_w, a1_b, e1_w, e1_b,
                          f1_w, f1_b, fa_w, fa_b);
    k_zassm<<<NB, 256>>>(e2_w, e2_b, f2_w, f2_b, bn2_g, bn2_b, bn3_g, bn3_b);

    {   // 1024x1024x768 : BM=128 -> 16x8 = 128 CTAs
        dim3 g(1024 / 64, NB / 128);
        k_gemm_relu_x2<128><<<g, 256>>>(p_z, w1, b1, p_c1, NB, 1024, 768);
    }
    {   // 1024x512x1024 : BM=64 -> 8x16 = 128 CTAs
        dim3 g(512 / 64, NB / 64);
        k_gemm_relu_x2<64><<<g, 256>>>(p_c1, w2, b2, p_c2, NB, 512, 1024);
    }
    {   // 1024x128x512 : BM=64 -> 2x16 = 32 CTAs
        dim3 g(128 / 64, NB / 64);
        k_gemm_relu_x2<64><<<g, 256>>>(p_c2, w3, b3, p_c3, NB, 128, 512);
    }
    k_fc4<<<NB / 8, 256>>>(w4, b4, out);
}

// round 14
// speedup vs baseline: 1.4660x; 1.0482x over previous
#include <cuda_runtime.h>
#include <math.h>

// ---------------------------------------------------------------------------
// Problem constants
// ---------------------------------------------------------------------------
#define NB   1024
#define NC   32
#define LIN  1024
#define LRAW 1041
#define LP   520
#define L1   257
#define L2   125
#define L3   31
#define L4   12
#define ZDIM 768

// ---------------------------------------------------------------------------
// Scratch
// ---------------------------------------------------------------------------
__device__ unsigned long long g_filt2[16 * 16];   // packed filter pairs {2p, 2p+1}
__device__ float  g_hp[NB * NC * LP];
__device__ double g_st1[2 * NC];
__device__ double g_st2[2 * NC];
__device__ double g_st3[2 * NC];
__device__ float  g_y1[NB * NC * L3];
__device__ float  g_y2[NB * NC * L3];
__device__ float  g_z [NB * ZDIM];
__device__ float  g_c1[NB * 1024];
__device__ float  g_c2[NB * 512];
__device__ float  g_c3sk[4 * NB * 128];           // split-K partials for FC3

// packed f32x2 ops
#define FFMA2(d, a, b) \
    asm volatile("fma.rn.f32x2 %0, %1, %2, %0;" : "+l"(d) : "l"(a), "l"(b))
#define ADD2(d, a) \
    asm volatile("add.rn.f32x2 %0, %0, %1;" : "+l"(d) : "l"(a))

__device__ __forceinline__ unsigned long long packdup(float v) {
    unsigned long long p;
    asm("mov.b64 %0, {%1, %1};" : "=l"(p) : "r"(__float_as_uint(v)));
    return p;
}
__device__ __forceinline__ unsigned long long packpair(float lo, float hi) {
    unsigned long long p;
    asm("mov.b64 %0, {%1, %2};" : "=l"(p)
        : "r"(__float_as_uint(lo)), "r"(__float_as_uint(hi)));
    return p;
}
__device__ __forceinline__ void unpack2(unsigned long long p, float& lo, float& hi) {
    unsigned a, b;
    asm("mov.b64 {%0, %1}, %2;" : "=r"(a), "=r"(b) : "l"(p));
    lo = __uint_as_float(a); hi = __uint_as_float(b);
}

// ---------------------------------------------------------------------------
// K0: zero stats + build packed Laplace filter pairs
// ---------------------------------------------------------------------------
__global__ void k_init(const float* __restrict__ la_a, const float* __restrict__ la_b) {
    int t = threadIdx.x;
    if (t < 2 * NC) { g_st1[t] = 0.0; g_st2[t] = 0.0; g_st3[t] = 0.0; }
    if (t < 256) {
        int pc = t >> 4, k = t & 15;
        const double A = 0.08, ep = 0.03, tal = 0.1, f = 50.0;
        const double w = 2.0 * 3.14159265358979323846 * f;
        const double q = 1.0 - ep * ep;
        double tk = (double)k / 15.0;
        float fv[2];
        #pragma unroll
        for (int h = 0; h < 2; h++) {
            int c = 2 * pc + h;
            double p  = tk - (double)la_b[c] / (double)la_a[c];
            double arg = w * (p - tal);
            fv[h] = (float)(A * exp(-ep / sqrt(q) * arg) * (-sin(arg)));
        }
        g_filt2[t] = packpair(fv[0], fv[1]);
    }
}

// ---------------------------------------------------------------------------
// K1: conv + la_bias + BN1 stats + avgpool(3,2) -> g_hp.
// Channel-paired FFMA2: two channels share the input window; 20 dup'd window
// values reused across all 16 filter taps.
// ---------------------------------------------------------------------------
__global__ __launch_bounds__(256) void k_conv(const float* __restrict__ x,
                                              const float* __restrict__ la_bias) {
    __shared__ float sxp[1060];

    int b = blockIdx.x;
    int t = threadIdx.x;

    for (int i = t; i < 1060; i += 256) {
        int xi = i - 16;
        sxp[i] = (xi >= 0 && xi < LIN) ? x[b * LIN + xi] : 0.0f;
    }
    __syncthreads();

    int w = t >> 5, lane = t & 31;

    #pragma unroll 1
    for (int cc = 0; cc < 2; cc++) {
        int pc = w * 2 + cc;             // pair index 0..15
        int c0 = 2 * pc, c1 = c0 + 1;
        unsigned long long fp[16];
        #pragma unroll
        for (int k = 0; k < 16; k++) fp[k] = g_filt2[pc * 16 + k];
        unsigned long long biasp = packpair(la_bias[c0], la_bias[c1]);

        unsigned long long s2 = 0ull, ss2 = 0ull;
        float* hprow0 = &g_hp[(b * NC + c0) * LP];
        float* hprow1 = &g_hp[(b * NC + c1) * LP];

        #pragma unroll 1
        for (int i = 0; i < 9; i++) {
            int base = 4 * lane + 128 * i;
            if (base > 1040) continue;
            float win[20];
            #pragma unroll
            for (int j = 0; j < 5; j++) {
                float4 q = *reinterpret_cast<const float4*>(&sxp[base + 4 * j]);
                win[4 * j + 0] = q.x; win[4 * j + 1] = q.y;
                win[4 * j + 2] = q.z; win[4 * j + 3] = q.w;
            }
            unsigned long long wd[20];
            #pragma unroll
            for (int m = 0; m < 20; m++) wd[m] = packdup(win[m]);

            unsigned long long r0 = biasp, r1 = biasp, r2 = biasp,
                               r3 = biasp, r4 = biasp;
            #pragma unroll
            for (int k = 0; k < 16; k++) {
                unsigned long long fk = fp[k];
                FFMA2(r0, wd[k    ], fk);
                FFMA2(r1, wd[k + 1], fk);
                FFMA2(r2, wd[k + 2], fk);
                FFMA2(r3, wd[k + 3], fk);
                FFMA2(r4, wd[k + 4], fk);
            }
            // BN1 stats (packed over the channel pair)
            if (base + 0 <= 1040) { ADD2(s2, r0); FFMA2(ss2, r0, r0); }
            if (base + 1 <= 1040) { ADD2(s2, r1); FFMA2(ss2, r1, r1); }
            if (base + 2 <= 1040) { ADD2(s2, r2); FFMA2(ss2, r2, r2); }
            if (base + 3 <= 1040) { ADD2(s2, r3); FFMA2(ss2, r3, r3); }
            // avgpool(3,2)
            int m0 = base >> 1;
            if (m0 <= 518) {
                unsigned long long p0 = r0, p1 = r2;
                ADD2(p0, r1); ADD2(p0, r2);
                ADD2(p1, r3); ADD2(p1, r4);
                unsigned long long third = packdup(1.0f / 3.0f);
                asm volatile("mul.rn.f32x2 %0, %0, %1;" : "+l"(p0) : "l"(third));
                asm volatile("mul.rn.f32x2 %0, %0, %1;" : "+l"(p1) : "l"(third));
                float a0, a1, b0v, b1v;
                unpack2(p0, a0, a1);     // (ch0 pool m0,   ch1 pool m0)
                unpack2(p1, b0v, b1v);   // (ch0 pool m0+1, ch1 pool m0+1)
                *reinterpret_cast<float2*>(&hprow0[m0]) = make_float2(a0, b0v);
                *reinterpret_cast<float2*>(&hprow1[m0]) = make_float2(a1, b1v);
            }
        }
        // unpack, then reduce each scalar across the warp
        float sl, sh, ssl, ssh;
        unpack2(s2, sl, sh);
        unpack2(ss2, ssl, ssh);
        #pragma unroll
        for (int o = 16; o > 0; o >>= 1) {
            sl  += __shfl_down_sync(0xffffffffu, sl,  o);
            sh  += __shfl_down_sync(0xffffffffu, sh,  o);
            ssl += __shfl_down_sync(0xffffffffu, ssl, o);
            ssh += __shfl_down_sync(0xffffffffu, ssh, o);
        }
        if (lane == 0) {
            atomicAdd(&g_st1[c0],      (double)sl);
            atomicAdd(&g_st1[NC + c0], (double)ssl);
            atomicAdd(&g_st1[c1],      (double)sh);
            atomicAdd(&g_st1[NC + c1], (double)ssh);
        }
    }
}

// ---------------------------------------------------------------------------
// K3: both branches. BN1 folded into layer-1 weights, cp.async prefetch.
// ---------------------------------------------------------------------------
__global__ __launch_bounds__(256) void k_branch(
    const float* __restrict__ bn1_g, const float* __restrict__ bn1_b,
    const float* __restrict__ a1_w, const float* __restrict__ a1_b,
    const float* __restrict__ e1_w, const float* __restrict__ e1_b,
    const float* __restrict__ f1_w, const float* __restrict__ f1_b,
    const float* __restrict__ fa_w, const float* __restrict__ fa_b) {

    __shared__ float sh[8][1328];

    int b = blockIdx.x;
    int t = threadIdx.x;
    int w = t >> 5, lane = t & 31;

    unsigned sbase = (unsigned)__cvta_generic_to_shared(&sh[0][0]);
    unsigned in_u32[2] = { sbase + (unsigned)(w * 1328) * 4u,
                           sbase + (unsigned)(w * 1328 + 528) * 4u };
    const float* inptr[2] = { &sh[w][0], &sh[w][528] };
    float* s1 = &sh[w][1056];

    int cbase = w * 4;

    {
        const float* src = &g_hp[(b * NC + cbase) * LP];
        #pragma unroll
        for (int i = 0; i < 5; i++) {
            int idx = lane + 32 * i;
            if (idx < 130)
                asm volatile("cp.async.ca.shared.global [%0], [%1], 16;"
                             :: "r"(in_u32[0] + idx * 16), "l"(src + idx * 4));
        }
        asm volatile("cp.async.commit_group;" ::: "memory");
    }

    #pragma unroll
    for (int cc = 0; cc < 4; cc++) {
        int c = cbase + cc;
        if (cc < 3) {
            const float* src = &g_hp[(b * NC + c + 1) * LP];
            unsigned dst = in_u32[(cc + 1) & 1];
            #pragma unroll
            for (int i = 0; i < 5; i++) {
                int idx = lane + 32 * i;
                if (idx < 130)
                    asm volatile("cp.async.ca.shared.global [%0], [%1], 16;"
                                 :: "r"(dst + idx * 16), "l"(src + idx * 4));
            }
            asm volatile("cp.async.commit_group;" ::: "memory");
            asm volatile("cp.async.wait_group 1;" ::: "memory");
        } else {
            asm volatile("cp.async.wait_group 0;" ::: "memory");
        }
        __syncwarp();
        const float* in = inptr[cc & 1];

        double Nn = (double)NB * (double)LRAW;
        double m = g_st1[c] / Nn;
        double var = g_st1[NC + c] / Nn - m * m;
        float sc = bn1_g[c] * rsqrtf((float)var + 1e-5f);
        float sf = bn1_b[c] - (float)m * sc;

        #pragma unroll 1
        for (int br = 0; br < 2; br++) {
            float w1r[8], acc1;
            {
                const float* wsrc = (br == 0) ? &a1_w[c * 8] : &f1_w[c * 8];
                float sum = 0.0f;
                #pragma unroll
                for (int j = 0; j < 8; j++) { w1r[j] = wsrc[j]; sum += w1r[j]; }
                float base = (br == 0) ? (a1_b[c] - sum) : (1.0f - f1_b[c]);
                acc1 = base + sf * sum;
                #pragma unroll
                for (int j = 0; j < 8; j++) w1r[j] *= sc;
            }

            #pragma unroll
            for (int i = 0; i < 2; i++) {
                int n0 = 4 * lane + 128 * i;
                int base = 2 * n0;
                float win[16];
                #pragma unroll
                for (int j = 0; j < 4; j++) {
                    float4 q = *reinterpret_cast<const float4*>(&in[base + 4 * j]);
                    win[4 * j + 0] = q.x; win[4 * j + 1] = q.y;
                    win[4 * j + 2] = q.z; win[4 * j + 3] = q.w;
                }
                float r0 = acc1, r1 = acc1, r2 = acc1, r3 = acc1;
                #pragma unroll
                for (int k = 0; k < 8; k++) {
                    float wk = w1r[k];
                    r0 = fmaf(win[k    ], wk, r0);
                    r1 = fmaf(win[k + 2], wk, r1);
                    r2 = fmaf(win[k + 4], wk, r2);
                    r3 = fmaf(win[k + 6], wk, r3);
                }
                float4 o;
                o.x = fmaxf(r0, 0.0f); o.y = fmaxf(r1, 0.0f);
                o.z = fmaxf(r2, 0.0f); o.w = fmaxf(r3, 0.0f);
                *reinterpret_cast<float4*>(&s1[n0]) = o;
            }
            __syncwarp();

            float w2r[8], acc2;
            if (br == 0) {
                #pragma unroll
                for (int j = 0; j < 8; j++) w2r[j] = e1_w[c * 8 + j];
                acc2 = 1.0f - e1_b[c];
            } else {
                float sum = 0.0f;
                #pragma unroll
                for (int j = 0; j < 8; j++) { w2r[j] = fa_w[c * 8 + j]; sum += w2r[j]; }
                acc2 = fa_b[c] - sum;
            }

            {
                int base = 8 * lane;
                float win[16];
                #pragma unroll
                for (int j = 0; j < 4; j++) {
                    float4 q = *reinterpret_cast<const float4*>(&s1[base + 4 * j]);
                    win[4 * j + 0] = q.x; win[4 * j + 1] = q.y;
                    win[4 * j + 2] = q.z; win[4 * j + 3] = q.w;
                }
                float r0 = acc2, r1 = acc2, r2 = acc2, r3 = acc2;
                #pragma unroll
                for (int k = 0; k < 8; k++) {
                    float wk = w2r[k];
                    r0 = fmaf(win[k    ], wk, r0);
                    r1 = fmaf(win[k + 2], wk, r1);
                    r2 = fmaf(win[k + 4], wk, r2);
                    r3 = fmaf(win[k + 6], wk, r3);
                }
                r0 = fmaxf(r0, 0.0f); r1 = fmaxf(r1, 0.0f);
                r2 = fmaxf(r2, 0.0f); r3 = fmaxf(r3, 0.0f);
                float y = fmaxf(fmaxf(r0, r1), fmaxf(r2, r3));
                float s = 0.0f, ss = 0.0f;
                if (lane < L3) {
                    if (br == 0) g_y1[(b * NC + c) * L3 + lane] = y;
                    else         g_y2[(b * NC + c) * L3 + lane] = y;
                    s = y; ss = y * y;
                }
                #pragma unroll
                for (int o = 16; o > 0; o >>= 1) {
                    s  += __shfl_down_sync(0xffffffffu, s,  o);
                    ss += __shfl_down_sync(0xffffffffu, ss, o);
                }
                if (lane == 0) {
                    double* st = (br == 0) ? g_st2 : g_st3;
                    atomicAdd(&st[c],      (double)s);
                    atomicAdd(&st[NC + c], (double)ss);
                }
            }
            __syncwarp();
        }
    }
}

// ---------------------------------------------------------------------------
// K5: BN2/BN3 (inline from stats) + final Eventually -> z (B,768)
// ---------------------------------------------------------------------------
__global__ __launch_bounds__(256) void k_zassm(
    const float* __restrict__ e2_w, const float* __restrict__ e2_b,
    const float* __restrict__ f2_w, const float* __restrict__ f2_b,
    const float* __restrict__ bn2_g, const float* __restrict__ bn2_b,
    const float* __restrict__ bn3_g, const float* __restrict__ bn3_b) {
    __shared__ float ssc[2][NC], ssh[2][NC];
    int b = blockIdx.x;
    int t = threadIdx.x;
    if (t < 64) {
        int br = t >> 5, c = t & 31;
        const double* st = br ? g_st3 : g_st2;
        float gam = br ? bn3_g[c] : bn2_g[c];
        float bet = br ? bn3_b[c] : bn2_b[c];
        double Nn = (double)NB * (double)L3;
        double m = st[c] / Nn;
        double v = st[NC + c] / Nn - m * m;
        float sc = gam * rsqrtf((float)v + 1e-5f);
        ssc[br][c] = sc;
        ssh[br][c] = bet - (float)m * sc;
    }
    __syncthreads();

    for (int o = t; o < ZDIM; o += 256) {
        int br  = o / 384;
        int rem = o - br * 384;
        int c = rem / L4, n = rem - c * L4;
        const float* y  = br ? &g_y2[(b * NC + c) * L3] : &g_y1[(b * NC + c) * L3];
        const float* wv = br ? &f2_w[c * 8] : &e2_w[c * 8];
        float bb = br ? f2_b[c] : e2_b[c];
        float scv = ssc[br][c], shv = ssh[br][c];
        float acc = 1.0f - bb;
        #pragma unroll
        for (int j = 0; j < 8; j++)
            acc = fmaf(fmaf(y[2 * n + j], scv, shv), wv[j], acc);
        g_z[b * ZDIM + o] = fmaxf(acc, 0.0f);
    }
}

// ---------------------------------------------------------------------------
// FFMA2 GEMM, double-buffered smem (1 sync per K-tile), optional split-K.
// FUSED=true: C = relu(A@W + bias). FUSED=false: raw partial store to
// Cc + blockIdx.z*splitStride, K-range [z*kcount, (z+1)*kcount).
// ---------------------------------------------------------------------------
template<int BM, bool FUSED>
__global__ __launch_bounds__(256) void k_gemm_x2(
    const float* __restrict__ A, const float* __restrict__ W,
    const float* __restrict__ bias, float* __restrict__ Cc,
    int M, int N, int Kfull, int kcount, int splitStride) {
    constexpr int R = BM / 16;
    constexpr int P = R / 2;
    constexpr int ALOADS = BM / 64;
    __shared__ float As[2][16][BM + 4];
    __shared__ float Ws[2][16][64];

    int tid = threadIdx.x;
    int tx = tid & 15, ty = tid >> 4;
    int rowBase = blockIdx.y * BM;
    int colBase = blockIdx.x * 64;
    int kstart  = blockIdx.z * kcount;
    float* Cz = Cc + (size_t)blockIdx.z * splitStride;

    int aRow[ALOADS], aC4[ALOADS];
    const float* Ap[ALOADS];
    #pragma unroll
    for (int i = 0; i < ALOADS; i++) {
        int idx = tid + i * 256;
        aRow[i] = idx >> 2;
        aC4[i]  = (idx & 3) * 4;
        Ap[i] = A + (size_t)(rowBase + aRow[i]) * Kfull + kstart + aC4[i];
    }
    int wRow = tid >> 4, wCol = (tid & 15) * 4;
    const float* Wp = W + (size_t)(kstart + wRow) * N + colBase + wCol;

    float4 avr[ALOADS];
    #pragma unroll
    for (int i = 0; i < ALOADS; i++) avr[i] = *reinterpret_cast<const float4*>(Ap[i]);
    float4 wvr = *reinterpret_cast<const float4*>(Wp);

    unsigned long long acc[P][4];
    #pragma unroll
    for (int i = 0; i < P; i++)
        #pragma unroll
        for (int j = 0; j < 4; j++) acc[i][j] = 0ull;

    int nt = kcount / 16;
    for (int tI = 0; tI < nt; tI++) {
        int buf = tI & 1;
        #pragma unroll
        for (int i = 0; i < ALOADS; i++) {
            As[buf][aC4[i] + 0][aRow[i]] = avr[i].x;
            As[buf][aC4[i] + 1][aRow[i]] = avr[i].y;
            As[buf][aC4[i] + 2][aRow[i]] = avr[i].z;
            As[buf][aC4[i] + 3][aRow[i]] = avr[i].w;
        }
        *reinterpret_cast<float4*>(&Ws[buf][wRow][wCol]) = wvr;
        __syncthreads();
        if (tI + 1 < nt) {
            int ko = (tI + 1) * 16;
            #pragma unroll
            for (int i = 0; i < ALOADS; i++)
                avr[i] = *reinterpret_cast<const float4*>(Ap[i] + ko);
            wvr = *reinterpret_cast<const float4*>(Wp + (size_t)ko * N);
        }
        #pragma unroll
        for (int k = 0; k < 16; k++) {
            unsigned long long ap[P];
            #pragma unroll
            for (int i = 0; i < P; i += 2) {
                ulonglong2 q = *reinterpret_cast<const ulonglong2*>(
                    &As[buf][k][ty * R + 4 * (i >> 1)]);
                ap[i] = q.x;
                if (i + 1 < P) ap[i + 1] = q.y;
            }
            float4 wv = *reinterpret_cast<const float4*>(&Ws[buf][k][tx * 4]);
            unsigned long long wp[4] = { packdup(wv.x), packdup(wv.y),
                                         packdup(wv.z), packdup(wv.w) };
            #pragma unroll
            for (int i = 0; i < P; i++)
                #pragma unroll
                for (int j = 0; j < 4; j++)
                    FFMA2(acc[i][j], ap[i], wp[j]);
        }
    }

    float bj[4] = { 0.f, 0.f, 0.f, 0.f };
    if (FUSED) {
        float4 bv = *reinterpret_cast<const float4*>(&bias[colBase + tx * 4]);
        bj[0] = bv.x; bj[1] = bv.y; bj[2] = bv.z; bj[3] = bv.w;
    }
    #pragma unroll
    for (int i = 0; i < P; i++) {
        int r0 = rowBase + ty * R + 2 * i;
        float lo[4], hi[4];
        #pragma unroll
        for (int j = 0; j < 4; j++) unpack2(acc[i][j], lo[j], hi[j]);
        float4 o0, o1;
        if (FUSED) {
            o0.x = fmaxf(lo[0] + bj[0], 0.0f); o0.y = fmaxf(lo[1] + bj[1], 0.0f);
            o0.z = fmaxf(lo[2] + bj[2], 0.0f); o0.w = fmaxf(lo[3] + bj[3], 0.0f);
            o1.x = fmaxf(hi[0] + bj[0], 0.0f); o1.y = fmaxf(hi[1] + bj[1], 0.0f);
            o1.z = fmaxf(hi[2] + bj[2], 0.0f); o1.w = fmaxf(hi[3] + bj[3], 0.0f);
        } else {
            o0 = make_float4(lo[0], lo[1], lo[2], lo[3]);
            o1 = make_float4(hi[0], hi[1], hi[2], hi[3]);
        }
        *reinterpret_cast<float4*>(&Cz[(size_t)r0 * N + colBase + tx * 4])       = o0;
        *reinterpret_cast<float4*>(&Cz[(size_t)(r0 + 1) * N + colBase + tx * 4]) = o1;
    }
}

// ---------------------------------------------------------------------------
// Final FC: sum 4 split-K partials of c3, +b3, relu, then (128x10) + b4, relu.
// ---------------------------------------------------------------------------
__global__ __launch_bounds__(256) void k_fc4(const float* __restrict__ w4,
                                             const float* __restrict__ b4,
                                             const float* __restrict__ b3,
                                             float* __restrict__ out) {
    const int S = NB * 128;
    int b = blockIdx.x * 8 + (threadIdx.x >> 5);
    int lane = threadIdx.x & 31;
    const float* base = &g_c3sk[b * 128];
    float v0 = base[lane]      + base[S + lane]      + base[2*S + lane]      + base[3*S + lane];
    float v1 = base[lane + 32] + base[S + lane + 32] + base[2*S + lane + 32] + base[3*S + lane + 32];
    float v2 = base[lane + 64] + base[S + lane + 64] + base[2*S + lane + 64] + base[3*S + lane + 64];
    float v3 = base[lane + 96] + base[S + lane + 96] + base[2*S + lane + 96] + base[3*S + lane + 96];
    v0 = fmaxf(v0 + b3[lane],      0.0f);
    v1 = fmaxf(v1 + b3[lane + 32], 0.0f);
    v2 = fmaxf(v2 + b3[lane + 64], 0.0f);
    v3 = fmaxf(v3 + b3[lane + 96], 0.0f);
    for (int j = 0; j < 10; j++) {
        float p = v0 * w4[lane * 10 + j]
                + v1 * w4[(lane + 32) * 10 + j]
                + v2 * w4[(lane + 64) * 10 + j]
                + v3 * w4[(lane + 96) * 10 + j];
        #pragma unroll
        for (int o = 16; o > 0; o >>= 1) p += __shfl_down_sync(0xffffffffu, p, o);
        if (lane == 0) out[b * 10 + j] = fmaxf(p + b4[j], 0.0f);
    }
}

// ---------------------------------------------------------------------------
// Launch
// ---------------------------------------------------------------------------
extern "C" void kernel_launch(void* const* d_in, const int* in_sizes, int n_in,
                              void* d_out, int out_size) {
    const float* x       = (const float*)d_in[0];
    const float* la_a    = (const float*)d_in[1];
    const float* la_b    = (const float*)d_in[2];
    const float* la_bias = (const float*)d_in[3];
    const float* bn1_g   = (const float*)d_in[4];
    const float* bn1_b   = (const float*)d_in[5];
    const float* a1_w    = (const float*)d_in[6];
    const float* a1_b    = (const float*)d_in[7];
    const float* e1_w    = (const float*)d_in[8];
    const float* e1_b    = (const float*)d_in[9];
    const float* bn2_g   = (const float*)d_in[10];
    const float* bn2_b   = (const float*)d_in[11];
    const float* e2_w    = (const float*)d_in[12];
    const float* e2_b    = (const float*)d_in[13];
    const float* f1_w    = (const float*)d_in[14];
    const float* f1_b    = (const float*)d_in[15];
    const float* fa_w    = (const float*)d_in[16];
    const float* fa_b    = (const float*)d_in[17];
    const float* bn3_g   = (const float*)d_in[18];
    const float* bn3_b   = (const float*)d_in[19];
    const float* f2_w    = (const float*)d_in[20];
    const float* f2_b    = (const float*)d_in[21];
    const float* w1      = (const float*)d_in[22];
    const float* b1      = (const float*)d_in[23];
    const float* w2      = (const float*)d_in[24];
    const float* b2      = (const float*)d_in[25];
    const float* w3      = (const float*)d_in[26];
    const float* b3      = (const float*)d_in[27];
    const float* w4      = (const float*)d_in[28];
    const float* b4      = (const float*)d_in[29];
    float* out = (float*)d_out;

    float *p_z = nullptr, *p_c1 = nullptr, *p_c2 = nullptr, *p_c3sk = nullptr;
    cudaGetSymbolAddress((void**)&p_z,    g_z);
    cudaGetSymbolAddress((void**)&p_c1,   g_c1);
    cudaGetSymbolAddress((void**)&p_c2,   g_c2);
    cudaGetSymbolAddress((void**)&p_c3sk, g_c3sk);

    k_init<<<1, 512>>>(la_a, la_b);
    k_conv<<<NB, 256>>>(x, la_bias);
    k_branch<<<NB, 256>>>(bn1_g, bn1_b, a1_w, a1_b, e1_w, e1_b,
                          f1_w, f1_b, fa_w, fa_b);
    k_zassm<<<NB, 256>>>(e2_w, e2_b, f2_w, f2_b, bn2_g, bn2_b, bn3_g, bn3_b);

    {   // 1024x1024x768
        dim3 g(1024 / 64, NB / 128, 1);
        k_gemm_x2<128, true><<<g, 256>>>(p_z, w1, b1, p_c1, NB, 1024, 768, 768, 0);
    }
    {   // 1024x512x1024
        dim3 g(512 / 64, NB / 64, 1);
        k_gemm_x2<64, true><<<g, 256>>>(p_c1, w2, b2, p_c2, NB, 512, 1024, 1024, 0);
    }
    {   // 1024x128x512 split-K x4 -> 128 CTAs
        dim3 g(128 / 64, NB / 64, 4);
        k_gemm_x2<64, false><<<g, 256>>>(p_c2, w3, nullptr, p_c3sk,
                                         NB, 128, 512, 128, NB * 128);
    }
    k_fc4<<<NB / 8, 256>>>(w4, b4, b3, out);
}

// round 17
// speedup vs baseline: 1.5454x; 1.0542x over previous
#include <cuda_runtime.h>
#include <cuda_bf16.h>
#include <math.h>

// ---------------------------------------------------------------------------
// Problem constants
// ---------------------------------------------------------------------------
#define NB   1024
#define NC   32
#define LIN  1024
#define LRAW 1041
#define LP   520
#define L1   257
#define L2   125
#define L3   31
#define L4   12
#define ZDIM 768

// ---------------------------------------------------------------------------
// Scratch
// ---------------------------------------------------------------------------
__device__ unsigned long long g_filt2[16 * 16];
__device__ float  g_hp[NB * NC * LP];
__device__ double g_st1[2 * NC];
__device__ double g_st2[2 * NC];
__device__ double g_st3[2 * NC];
__device__ float  g_y1[NB * NC * L3];
__device__ float  g_y2[NB * NC * L3];
__device__ float  g_c3sk[4 * NB * 128];           // split-K partials for FC3

// bf16-split activations / weights
__device__ __nv_bfloat16 g_zh[NB * ZDIM],  g_zl[NB * ZDIM];
__device__ __nv_bfloat16 g_c1h[NB * 1024], g_c1l[NB * 1024];
__device__ __nv_bfloat16 g_c2h[NB * 512],  g_c2l[NB * 512];
__device__ __nv_bfloat16 g_w1h[768 * 1024], g_w1l[768 * 1024];
__device__ __nv_bfloat16 g_w2h[1024 * 512], g_w2l[1024 * 512];
__device__ __nv_bfloat16 g_w3h[512 * 128],  g_w3l[512 * 128];

// packed f32x2 ops (k_conv)
#define FFMA2(d, a, b) \
    asm volatile("fma.rn.f32x2 %0, %1, %2, %0;" : "+l"(d) : "l"(a), "l"(b))
#define ADD2(d, a) \
    asm volatile("add.rn.f32x2 %0, %0, %1;" : "+l"(d) : "l"(a))

__device__ __forceinline__ unsigned long long packdup(float v) {
    unsigned long long p;
    asm("mov.b64 %0, {%1, %1};" : "=l"(p) : "r"(__float_as_uint(v)));
    return p;
}
__device__ __forceinline__ unsigned long long packpair(float lo, float hi) {
    unsigned long long p;
    asm("mov.b64 %0, {%1, %2};" : "=l"(p)
        : "r"(__float_as_uint(lo)), "r"(__float_as_uint(hi)));
    return p;
}
__device__ __forceinline__ void unpack2(unsigned long long p, float& lo, float& hi) {
    unsigned a, b;
    asm("mov.b64 {%0, %1}, %2;" : "=r"(a), "=r"(b) : "l"(p));
    lo = __uint_as_float(a); hi = __uint_as_float(b);
}

// bf16 split helpers
__device__ __forceinline__ void bf16split(float x, __nv_bfloat16& h, __nv_bfloat16& l) {
    h = __float2bfloat16(x);
    l = __float2bfloat16(x - __bfloat162float(h));
}
__device__ __forceinline__ unsigned packbf2(__nv_bfloat16 lo, __nv_bfloat16 hi) {
    __nv_bfloat162 v; v.x = lo; v.y = hi;
    return *reinterpret_cast<unsigned*>(&v);
}

// tensor-core macros
#define LDSM4(r, addr) \
    asm volatile("ldmatrix.sync.aligned.m8n8.x4.shared.b16 {%0,%1,%2,%3}, [%4];" \
        : "=r"((r)[0]), "=r"((r)[1]), "=r"((r)[2]), "=r"((r)[3]) : "r"(addr))
#define LDSM4T(r, addr) \
    asm volatile("ldmatrix.sync.aligned.m8n8.x4.trans.shared.b16 {%0,%1,%2,%3}, [%4];" \
        : "=r"((r)[0]), "=r"((r)[1]), "=r"((r)[2]), "=r"((r)[3]) : "r"(addr))
#define MMA_BF16(c, a, b0, b1) \
    asm volatile("mma.sync.aligned.m16n8k16.row.col.f32.bf16.bf16.f32 " \
        "{%0,%1,%2,%3}, {%4,%5,%6,%7}, {%8,%9}, {%0,%1,%2,%3};" \
        : "+f"((c)[0]), "+f"((c)[1]), "+f"((c)[2]), "+f"((c)[3]) \
        : "r"((a)[0]), "r"((a)[1]), "r"((a)[2]), "r"((a)[3]), "r"(b0), "r"(b1))

// ---------------------------------------------------------------------------
// K0: zero stats + build packed Laplace filter pairs
// ---------------------------------------------------------------------------
__global__ void k_init(const float* __restrict__ la_a, const float* __restrict__ la_b) {
    int t = threadIdx.x;
    if (t < 2 * NC) { g_st1[t] = 0.0; g_st2[t] = 0.0; g_st3[t] = 0.0; }
    if (t < 256) {
        int pc = t >> 4, k = t & 15;
        const double A = 0.08, ep = 0.03, tal = 0.1, f = 50.0;
        const double w = 2.0 * 3.14159265358979323846 * f;
        const double q = 1.0 - ep * ep;
        double tk = (double)k / 15.0;
        float fv[2];
        #pragma unroll
        for (int h = 0; h < 2; h++) {
            int c = 2 * pc + h;
            double p  = tk - (double)la_b[c] / (double)la_a[c];
            double arg = w * (p - tal);
            fv[h] = (float)(A * exp(-ep / sqrt(q) * arg) * (-sin(arg)));
        }
        g_filt2[t] = packpair(fv[0], fv[1]);
    }
}

// ---------------------------------------------------------------------------
// K0b: split w1/w2/w3 into bf16 hi/lo arrays (once per launch).
// ---------------------------------------------------------------------------
__global__ __launch_bounds__(256) void k_wconv(const float* __restrict__ w1,
                                               const float* __restrict__ w2,
                                               const float* __restrict__ w3) {
    int e = (blockIdx.x * 256 + threadIdx.x) * 4;
    const float* src; __nv_bfloat16 *dh, *dl; int off;
    if (e < 786432)        { src = w1; dh = g_w1h; dl = g_w1l; off = e; }
    else if (e < 1310720)  { src = w2; dh = g_w2h; dl = g_w2l; off = e - 786432; }
    else                   { src = w3; dh = g_w3h; dl = g_w3l; off = e - 1310720; }
    float4 v = *reinterpret_cast<const float4*>(src + off);
    __nv_bfloat16 h0, l0, h1, l1, h2, l2, h3, l3;
    bf16split(v.x, h0, l0); bf16split(v.y, h1, l1);
    bf16split(v.z, h2, l2); bf16split(v.w, h3, l3);
    uint2 ph = make_uint2(packbf2(h0, h1), packbf2(h2, h3));
    uint2 pl = make_uint2(packbf2(l0, l1), packbf2(l2, l3));
    *reinterpret_cast<uint2*>(dh + off) = ph;
    *reinterpret_cast<uint2*>(dl + off) = pl;
}

// ---------------------------------------------------------------------------
// K1: conv + la_bias + BN1 stats + avgpool(3,2) -> g_hp. (channel-paired FFMA2)
// ---------------------------------------------------------------------------
__global__ __launch_bounds__(256) void k_conv(const float* __restrict__ x,
                                              const float* __restrict__ la_bias) {
    __shared__ float sxp[1060];

    int b = blockIdx.x;
    int t = threadIdx.x;

    for (int i = t; i < 1060; i += 256) {
        int xi = i - 16;
        sxp[i] = (xi >= 0 && xi < LIN) ? x[b * LIN + xi] : 0.0f;
    }
    __syncthreads();

    int w = t >> 5, lane = t & 31;

    #pragma unroll 1
    for (int cc = 0; cc < 2; cc++) {
        int pc = w * 2 + cc;
        int c0 = 2 * pc, c1 = c0 + 1;
        unsigned long long fp[16];
        #pragma unroll
        for (int k = 0; k < 16; k++) fp[k] = g_filt2[pc * 16 + k];
        unsigned long long biasp = packpair(la_bias[c0], la_bias[c1]);

        unsigned long long s2 = 0ull, ss2 = 0ull;
        float* hprow0 = &g_hp[(b * NC + c0) * LP];
        float* hprow1 = &g_hp[(b * NC + c1) * LP];

        #pragma unroll 1
        for (int i = 0; i < 9; i++) {
            int base = 4 * lane + 128 * i;
            if (base > 1040) continue;
            float win[20];
            #pragma unroll
            for (int j = 0; j < 5; j++) {
                float4 q = *reinterpret_cast<const float4*>(&sxp[base + 4 * j]);
                win[4 * j + 0] = q.x; win[4 * j + 1] = q.y;
                win[4 * j + 2] = q.z; win[4 * j + 3] = q.w;
            }
            unsigned long long wd[20];
            #pragma unroll
            for (int m = 0; m < 20; m++) wd[m] = packdup(win[m]);

            unsigned long long r0 = biasp, r1 = biasp, r2 = biasp,
                               r3 = biasp, r4 = biasp;
            #pragma unroll
            for (int k = 0; k < 16; k++) {
                unsigned long long fk = fp[k];
                FFMA2(r0, wd[k    ], fk);
                FFMA2(r1, wd[k + 1], fk);
                FFMA2(r2, wd[k + 2], fk);
                FFMA2(r3, wd[k + 3], fk);
                FFMA2(r4, wd[k + 4], fk);
            }
            if (base + 0 <= 1040) { ADD2(s2, r0); FFMA2(ss2, r0, r0); }
            if (base + 1 <= 1040) { ADD2(s2, r1); FFMA2(ss2, r1, r1); }
            if (base + 2 <= 1040) { ADD2(s2, r2); FFMA2(ss2, r2, r2); }
            if (base + 3 <= 1040) { ADD2(s2, r3); FFMA2(ss2, r3, r3); }
            int m0 = base >> 1;
            if (m0 <= 518) {
                unsigned long long p0 = r0, p1 = r2;
                ADD2(p0, r1); ADD2(p0, r2);
                ADD2(p1, r3); ADD2(p1, r4);
                unsigned long long third = packdup(1.0f / 3.0f);
                asm volatile("mul.rn.f32x2 %0, %0, %1;" : "+l"(p0) : "l"(third));
                asm volatile("mul.rn.f32x2 %0, %0, %1;" : "+l"(p1) : "l"(third));
                float a0, a1, b0v, b1v;
                unpack2(p0, a0, a1);
                unpack2(p1, b0v, b1v);
                *reinterpret_cast<float2*>(&hprow0[m0]) = make_float2(a0, b0v);
                *reinterpret_cast<float2*>(&hprow1[m0]) = make_float2(a1, b1v);
            }
        }
        float sl, sh, ssl, ssh;
        unpack2(s2, sl, sh);
        unpack2(ss2, ssl, ssh);
        #pragma unroll
        for (int o = 16; o > 0; o >>= 1) {
            sl  += __shfl_down_sync(0xffffffffu, sl,  o);
            sh  += __shfl_down_sync(0xffffffffu, sh,  o);
            ssl += __shfl_down_sync(0xffffffffu, ssl, o);
            ssh += __shfl_down_sync(0xffffffffu, ssh, o);
        }
        if (lane == 0) {
            atomicAdd(&g_st1[c0],      (double)sl);
            atomicAdd(&g_st1[NC + c0], (double)ssl);
            atomicAdd(&g_st1[c1],      (double)sh);
            atomicAdd(&g_st1[NC + c1], (double)ssh);
        }
    }
}

// ---------------------------------------------------------------------------
// K3: both branches. BN1 folded into layer-1 weights, cp.async prefetch.
// ---------------------------------------------------------------------------
__global__ __launch_bounds__(256) void k_branch(
    const float* __restrict__ bn1_g, const float* __restrict__ bn1_b,
    const float* __restrict__ a1_w, const float* __restrict__ a1_b,
    const float* __restrict__ e1_w, const float* __restrict__ e1_b,
    const float* __restrict__ f1_w, const float* __restrict__ f1_b,
    const float* __restrict__ fa_w, const float* __restrict__ fa_b) {

    __shared__ float sh[8][1328];

    int b = blockIdx.x;
    int t = threadIdx.x;
    int w = t >> 5, lane = t & 31;

    unsigned sbase = (unsigned)__cvta_generic_to_shared(&sh[0][0]);
    unsigned in_u32[2] = { sbase + (unsigned)(w * 1328) * 4u,
                           sbase + (unsigned)(w * 1328 + 528) * 4u };
    const float* inptr[2] = { &sh[w][0], &sh[w][528] };
    float* s1 = &sh[w][1056];

    int cbase = w * 4;

    {
        const float* src = &g_hp[(b * NC + cbase) * LP];
        #pragma unroll
        for (int i = 0; i < 5; i++) {
            int idx = lane + 32 * i;
            if (idx < 130)
                asm volatile("cp.async.ca.shared.global [%0], [%1], 16;"
                             :: "r"(in_u32[0] + idx * 16), "l"(src + idx * 4));
        }
        asm volatile("cp.async.commit_group;" ::: "memory");
    }

    #pragma unroll
    for (int cc = 0; cc < 4; cc++) {
        int c = cbase + cc;
        if (cc < 3) {
            const float* src = &g_hp[(b * NC + c + 1) * LP];
            unsigned dst = in_u32[(cc + 1) & 1];
            #pragma unroll
            for (int i = 0; i < 5; i++) {
                int idx = lane + 32 * i;
                if (idx < 130)
                    asm volatile("cp.async.ca.shared.global [%0], [%1], 16;"
                                 :: "r"(dst + idx * 16), "l"(src + idx * 4));
            }
            asm volatile("cp.async.commit_group;" ::: "memory");
            asm volatile("cp.async.wait_group 1;" ::: "memory");
        } else {
            asm volatile("cp.async.wait_group 0;" ::: "memory");
        }
        __syncwarp();
        const float* in = inptr[cc & 1];

        double Nn = (double)NB * (double)LRAW;
        double m = g_st1[c] / Nn;
        double var = g_st1[NC + c] / Nn - m * m;
        float sc = bn1_g[c] * rsqrtf((float)var + 1e-5f);
        float sf = bn1_b[c] - (float)m * sc;

        #pragma unroll 1
        for (int br = 0; br < 2; br++) {
            float w1r[8], acc1;
            {
                const float* wsrc = (br == 0) ? &a1_w[c * 8] : &f1_w[c * 8];
                float sum = 0.0f;
                #pragma unroll
                for (int j = 0; j < 8; j++) { w1r[j] = wsrc[j]; sum += w1r[j]; }
                float base = (br == 0) ? (a1_b[c] - sum) : (1.0f - f1_b[c]);
                acc1 = base + sf * sum;
                #pragma unroll
                for (int j = 0; j < 8; j++) w1r[j] *= sc;
            }

            #pragma unroll
            for (int i = 0; i < 2; i++) {
                int n0 = 4 * lane + 128 * i;
                int base = 2 * n0;
                float win[16];
                #pragma unroll
                for (int j = 0; j < 4; j++) {
                    float4 q = *reinterpret_cast<const float4*>(&in[base + 4 * j]);
                    win[4 * j + 0] = q.x; win[4 * j + 1] = q.y;
                    win[4 * j + 2] = q.z; win[4 * j + 3] = q.w;
                }
                float r0 = acc1, r1 = acc1, r2 = acc1, r3 = acc1;
                #pragma unroll
                for (int k = 0; k < 8; k++) {
                    float wk = w1r[k];
                    r0 = fmaf(win[k    ], wk, r0);
                    r1 = fmaf(win[k + 2], wk, r1);
                    r2 = fmaf(win[k + 4], wk, r2);
                    r3 = fmaf(win[k + 6], wk, r3);
                }
                float4 o;
                o.x = fmaxf(r0, 0.0f); o.y = fmaxf(r1, 0.0f);
                o.z = fmaxf(r2, 0.0f); o.w = fmaxf(r3, 0.0f);
                *reinterpret_cast<float4*>(&s1[n0]) = o;
            }
            __syncwarp();

            float w2r[8], acc2;
            if (br == 0) {
                #pragma unroll
                for (int j = 0; j < 8; j++) w2r[j] = e1_w[c * 8 + j];
                acc2 = 1.0f - e1_b[c];
            } else {
                float sum = 0.0f;
                #pragma unroll
                for (int j = 0; j < 8; j++) { w2r[j] = fa_w[c * 8 + j]; sum += w2r[j]; }
                acc2 = fa_b[c] - sum;
            }

            {
                int base = 8 * lane;
                float win[16];
                #pragma unroll
                for (int j = 0; j < 4; j++) {
                    float4 q = *reinterpret_cast<const float4*>(&s1[base + 4 * j]);
                    win[4 * j + 0] = q.x; win[4 * j + 1] = q.y;
                    win[4 * j + 2] = q.z; win[4 * j + 3] = q.w;
                }
                float r0 = acc2, r1 = acc2, r2 = acc2, r3 = acc2;
                #pragma unroll
                for (int k = 0; k < 8; k++) {
                    float wk = w2r[k];
                    r0 = fmaf(win[k    ], wk, r0);
                    r1 = fmaf(win[k + 2], wk, r1);
                    r2 = fmaf(win[k + 4], wk, r2);
                    r3 = fmaf(win[k + 6], wk, r3);
                }
                r0 = fmaxf(r0, 0.0f); r1 = fmaxf(r1, 0.0f);
                r2 = fmaxf(r2, 0.0f); r3 = fmaxf(r3, 0.0f);
                float y = fmaxf(fmaxf(r0, r1), fmaxf(r2, r3));
                float s = 0.0f, ss = 0.0f;
                if (lane < L3) {
                    if (br == 0) g_y1[(b * NC + c) * L3 + lane] = y;
                    else         g_y2[(b * NC + c) * L3 + lane] = y;
                    s = y; ss = y * y;
                }
                #pragma unroll
                for (int o = 16; o > 0; o >>= 1) {
                    s  += __shfl_down_sync(0xffffffffu, s,  o);
                    ss += __shfl_down_sync(0xffffffffu, ss, o);
                }
                if (lane == 0) {
                    double* st = (br == 0) ? g_st2 : g_st3;
                    atomicAdd(&st[c],      (double)s);
                    atomicAdd(&st[NC + c], (double)ss);
                }
            }
            __syncwarp();
        }
    }
}

// ---------------------------------------------------------------------------
// K5: BN2/BN3 (inline from stats) + final Eventually -> split-bf16 z
// ---------------------------------------------------------------------------
__global__ __launch_bounds__(256) void k_zassm(
    const float* __restrict__ e2_w, const float* __restrict__ e2_b,
    const float* __restrict__ f2_w, const float* __restrict__ f2_b,
    const float* __restrict__ bn2_g, const float* __restrict__ bn2_b,
    const float* __restrict__ bn3_g, const float* __restrict__ bn3_b) {
    __shared__ float ssc[2][NC], ssh[2][NC];
    int b = blockIdx.x;
    int t = threadIdx.x;
    if (t < 64) {
        int br = t >> 5, c = t & 31;
        const double* st = br ? g_st3 : g_st2;
        float gam = br ? bn3_g[c] : bn2_g[c];
        float bet = br ? bn3_b[c] : bn2_b[c];
        double Nn = (double)NB * (double)L3;
        double m = st[c] / Nn;
        double v = st[NC + c] / Nn - m * m;
        float sc = gam * rsqrtf((float)v + 1e-5f);
        ssc[br][c] = sc;
        ssh[br][c] = bet - (float)m * sc;
    }
    __syncthreads();

    for (int o = t; o < ZDIM; o += 256) {
        int br  = o / 384;
        int rem = o - br * 384;
        int c = rem / L4, n = rem - c * L4;
        const float* y  = br ? &g_y2[(b * NC + c) * L3] : &g_y1[(b * NC + c) * L3];
        const float* wv = br ? &f2_w[c * 8] : &e2_w[c * 8];
        float bb = br ? f2_b[c] : e2_b[c];
        float scv = ssc[br][c], shv = ssh[br][c];
        float acc = 1.0f - bb;
        #pragma unroll
        for (int j = 0; j < 8; j++)
            acc = fmaf(fmaf(y[2 * n + j], scv, shv), wv[j], acc);
        float v = fmaxf(acc, 0.0f);
        __nv_bfloat16 h, l;
        bf16split(v, h, l);
        g_zh[b * ZDIM + o] = h;
        g_zl[b * ZDIM + o] = l;
    }
}

// ---------------------------------------------------------------------------
// bf16-split tensor-core GEMM.
// C = A @ W (+bias, relu) with A = Ah+Al, W = Bh+Bl bf16 splits:
//   D = Ah@Bh + Ah@Bl + Al@Bh   (Al@Bl dropped, ~2^-16 relative)
// BM in {128, 64}; BN = 64; KT = 16; 256 threads.
// BM=128: 8 warps stacked in M, each covers all 64 N (8 n-tiles).
// BM=64:  4x2 warps (M x N), each covers 32 N (4 n-tiles).
// FUSED: epilogue writes split-bf16 output arrays (Ch, Cl).
// !FUSED: raw fp32 partials to Cp + blockIdx.z * splitStride.
// ---------------------------------------------------------------------------
template<int BM, bool FUSED>
__global__ __launch_bounds__(256) void k_gemm_bf16(
    const __nv_bfloat16* __restrict__ Ah, const __nv_bfloat16* __restrict__ Al,
    const __nv_bfloat16* __restrict__ Bh, const __nv_bfloat16* __restrict__ Bl,
    const float* __restrict__ bias,
    __nv_bfloat16* __restrict__ Ch, __nv_bfloat16* __restrict__ Cl,
    float* __restrict__ Cp,
    int M, int N, int K, int kcount, int splitStride) {

    constexpr int ASTRIDE = 24;              // bf16 units; 48B rows -> conflict-free
    constexpr int BSTRIDE = 72;              // 144B rows -> conflict-free
    constexpr int ATILE = BM * ASTRIDE;
    constexpr int BTILE = 16 * BSTRIDE;
    constexpr int NTILES = (BM == 128) ? 8 : 4;

    __shared__ __align__(16) unsigned short smA[2 * 2 * ATILE];
    __shared__ __align__(16) unsigned short smB[2 * 2 * BTILE];

    int tid = threadIdx.x;
    int w = tid >> 5, lane = tid & 31;
    int rowBase = blockIdx.y * BM;
    int colBase = blockIdx.x * 64;
    int kstart  = blockIdx.z * kcount;

    // warp tiling
    int mbase, nwBase;
    if (BM == 128) { mbase = w * 16; nwBase = 0; }
    else           { mbase = (w & 3) * 16; nwBase = (w >> 2) * 32; }

    // ---- loader setup ----
    // A: rows of 16 bf16 per k-tile; 2 threads per row (8 bf16 each).
    int aRow, aK; bool aHi = true;
    if (BM == 128) { aRow = tid >> 1; aK = (tid & 1) * 8; }
    else { aHi = tid < 128; int tt = tid & 127; aRow = tt >> 1; aK = (tt & 1) * 8; }
    const __nv_bfloat16* gAh = Ah + (size_t)(rowBase + aRow) * K + kstart + aK;
    const __nv_bfloat16* gAl = Al + (size_t)(rowBase + aRow) * K + kstart + aK;
    // B: 16 k-rows x 64 n; 4 bf16 per thread.
    int brow = tid >> 4, bcol = (tid & 15) * 4;
    const __nv_bfloat16* gBh = Bh + (size_t)(kstart + brow) * N + colBase + bcol;
    const __nv_bfloat16* gBl = Bl + (size_t)(kstart + brow) * N + colBase + bcol;

    uint4 pah, pal; uint2 pbh, pbl;
    if (BM == 128) {
        pah = *reinterpret_cast<const uint4*>(gAh);
        pal = *reinterpret_cast<const uint4*>(gAl);
    } else {
        pah = aHi ? *reinterpret_cast<const uint4*>(gAh)
                  : *reinterpret_cast<const uint4*>(gAl);
    }
    pbh = *reinterpret_cast<const uint2*>(gBh);
    pbl = *reinterpret_cast<const uint2*>(gBl);

    // fragment smem addresses (lane-dependent parts)
    unsigned smA_b = (unsigned)__cvta_generic_to_shared(smA);
    unsigned smB_b = (unsigned)__cvta_generic_to_shared(smB);
    int mi = lane >> 3;
    unsigned aFrag = smA_b +
        (unsigned)(((mbase + (mi & 1) * 8 + (lane & 7)) * ASTRIDE + (mi >> 1) * 8) * 2);
    unsigned bFrag = smB_b +
        (unsigned)((((mi & 1) * 8 + (lane & 7)) * BSTRIDE + ((mi >> 1) * 8)) * 2);

    float acc[NTILES][4];
    #pragma unroll
    for (int i = 0; i < NTILES; i++)
        #pragma unroll
        for (int j = 0; j < 4; j++) acc[i][j] = 0.0f;

    int nt = kcount / 16;
    for (int tI = 0; tI < nt; tI++) {
        int buf = tI & 1;
        // store staged tile
        if (BM == 128) {
            *reinterpret_cast<uint4*>(&smA[(buf * 2 + 0) * ATILE + aRow * ASTRIDE + aK]) = pah;
            *reinterpret_cast<uint4*>(&smA[(buf * 2 + 1) * ATILE + aRow * ASTRIDE + aK]) = pal;
        } else {
            *reinterpret_cast<uint4*>(&smA[(buf * 2 + (aHi ? 0 : 1)) * ATILE
                                           + aRow * ASTRIDE + aK]) = pah;
        }
        *reinterpret_cast<uint2*>(&smB[(buf * 2 + 0) * BTILE + brow * BSTRIDE + bcol]) = pbh;
        *reinterpret_cast<uint2*>(&smB[(buf * 2 + 1) * BTILE + brow * BSTRIDE + bcol]) = pbl;
        __syncthreads();
        // prefetch next
        if (tI + 1 < nt) {
            int ko = (tI + 1) * 16;
            if (BM == 128) {
                pah = *reinterpret_cast<const uint4*>(gAh + ko);
                pal = *reinterpret_cast<const uint4*>(gAl + ko);
            } else {
                pah = aHi ? *reinterpret_cast<const uint4*>(gAh + ko)
                          : *reinterpret_cast<const uint4*>(gAl + ko);
            }
            pbh = *reinterpret_cast<const uint2*>(gBh + (size_t)ko * N);
            pbl = *reinterpret_cast<const uint2*>(gBl + (size_t)ko * N);
        }
        // compute
        unsigned aH[4], aL[4];
        LDSM4(aH, aFrag + (unsigned)((buf * 2 + 0) * ATILE * 2));
        LDSM4(aL, aFrag + (unsigned)((buf * 2 + 1) * ATILE * 2));
        #pragma unroll
        for (int np = 0; np < NTILES / 2; np++) {
            unsigned bH[4], bL[4];
            unsigned boff = (unsigned)((nwBase + np * 16) * 2);
            LDSM4T(bH, bFrag + (unsigned)((buf * 2 + 0) * BTILE * 2) + boff);
            LDSM4T(bL, bFrag + (unsigned)((buf * 2 + 1) * BTILE * 2) + boff);
            MMA_BF16(acc[2 * np],     aH, bH[0], bH[1]);
            MMA_BF16(acc[2 * np],     aH, bL[0], bL[1]);
            MMA_BF16(acc[2 * np],     aL, bH[0], bH[1]);
            MMA_BF16(acc[2 * np + 1], aH, bH[2], bH[3]);
            MMA_BF16(acc[2 * np + 1], aH, bL[2], bL[3]);
            MMA_BF16(acc[2 * np + 1], aL, bH[2], bH[3]);
        }
    }

    // epilogue
    int g = lane >> 2, tq = lane & 3;
    int r0 = rowBase + mbase + g;
    #pragma unroll
    for (int j = 0; j < NTILES; j++) {
        int c = colBase + nwBase + j * 8 + 2 * tq;
        if (FUSED) {
            float b0v = bias[c], b1v = bias[c + 1];
            float v00 = fmaxf(acc[j][0] + b0v, 0.0f);
            float v01 = fmaxf(acc[j][1] + b1v, 0.0f);
            float v10 = fmaxf(acc[j][2] + b0v, 0.0f);
            float v11 = fmaxf(acc[j][3] + b1v, 0.0f);
            __nv_bfloat16 h00, l00, h01, l01, h10, l10, h11, l11;
            bf16split(v00, h00, l00); bf16split(v01, h01, l01);
            bf16split(v10, h10, l10); bf16split(v11, h11, l11);
            *reinterpret_cast<unsigned*>(Ch + (size_t)r0 * N + c)       = packbf2(h00, h01);
            *reinterpret_cast<unsigned*>(Cl + (size_t)r0 * N + c)       = packbf2(l00, l01);
            *reinterpret_cast<unsigned*>(Ch + (size_t)(r0 + 8) * N + c) = packbf2(h10, h11);
            *reinterpret_cast<unsigned*>(Cl + (size_t)(r0 + 8) * N + c) = packbf2(l10, l11);
        } else {
            float* Cz = Cp + (size_t)blockIdx.z * splitStride;
            *reinterpret_cast<float2*>(Cz + (size_t)r0 * N + c) =
                make_float2(acc[j][0], acc[j][1]);
            *reinterpret_cast<float2*>(Cz + (size_t)(r0 + 8) * N + c) =
                make_float2(acc[j][2], acc[j][3]);
        }
    }
}

// ---------------------------------------------------------------------------
// Final FC: sum 4 split-K partials of c3, +b3, relu, then (128x10) + b4, relu.
// ---------------------------------------------------------------------------
__global__ __launch_bounds__(256) void k_fc4(const float* __restrict__ w4,
                                             const float* __restrict__ b4,
                                             const float* __restrict__ b3,
                                             float* __restrict__ out) {
    const int S = NB * 128;
    int b = blockIdx.x * 8 + (threadIdx.x >> 5);
    int lane = threadIdx.x & 31;
    const float* base = &g_c3sk[b * 128];
    float v0 = base[lane]      + base[S + lane]      + base[2*S + lane]      + base[3*S + lane];
    float v1 = base[lane + 32] + base[S + lane + 32] + base[2*S + lane + 32] + base[3*S + lane + 32];
    float v2 = base[lane + 64] + base[S + lane + 64] + base[2*S + lane + 64] + base[3*S + lane + 64];
    float v3 = base[lane + 96] + base[S + lane + 96] + base[2*S + lane + 96] + base[3*S + lane + 96];
    v0 = fmaxf(v0 + b3[lane],      0.0f);
    v1 = fmaxf(v1 + b3[lane + 32], 0.0f);
    v2 = fmaxf(v2 + b3[lane + 64], 0.0f);
    v3 = fmaxf(v3 + b3[lane + 96], 0.0f);
    for (int j = 0; j < 10; j++) {
        float p = v0 * w4[lane * 10 + j]
                + v1 * w4[(lane + 32) * 10 + j]
                + v2 * w4[(lane + 64) * 10 + j]
                + v3 * w4[(lane + 96) * 10 + j];
        #pragma unroll
        for (int o = 16; o > 0; o >>= 1) p += __shfl_down_sync(0xffffffffu, p, o);
        if (lane == 0) out[b * 10 + j] = fmaxf(p + b4[j], 0.0f);
    }
}

// ---------------------------------------------------------------------------
// Launch
// ---------------------------------------------------------------------------
extern "C" void kernel_launch(void* const* d_in, const int* in_sizes, int n_in,
                              void* d_out, int out_size) {
    const float* x       = (const float*)d_in[0];
    const float* la_a    = (const float*)d_in[1];
    const float* la_b    = (const float*)d_in[2];
    const float* la_bias = (const float*)d_in[3];
    const float* bn1_g   = (const float*)d_in[4];
    const float* bn1_b   = (const float*)d_in[5];
    const float* a1_w    = (const float*)d_in[6];
    const float* a1_b    = (const float*)d_in[7];
    const float* e1_w    = (const float*)d_in[8];
    const float* e1_b    = (const float*)d_in[9];
    const float* bn2_g   = (const float*)d_in[10];
    const float* bn2_b   = (const float*)d_in[11];
    const float* e2_w    = (const float*)d_in[12];
    const float* e2_b    = (const float*)d_in[13];
    const float* f1_w    = (const float*)d_in[14];
    const float* f1_b    = (const float*)d_in[15];
    const float* fa_w    = (const float*)d_in[16];
    const float* fa_b    = (const float*)d_in[17];
    const float* bn3_g   = (const float*)d_in[18];
    const float* bn3_b   = (const float*)d_in[19];
    const float* f2_w    = (const float*)d_in[20];
    const float* f2_b    = (const float*)d_in[21];
    const float* w1      = (const float*)d_in[22];
    const float* b1      = (const float*)d_in[23];
    const float* w2      = (const float*)d_in[24];
    const float* b2      = (const float*)d_in[25];
    const float* w3      = (const float*)d_in[26];
    const float* b3      = (const float*)d_in[27];
    const float* w4      = (const float*)d_in[28];
    const float* b4      = (const float*)d_in[29];
    float* out = (float*)d_out;

    __nv_bfloat16 *p_zh, *p_zl, *p_c1h, *p_c1l, *p_c2h, *p_c2l;
    __nv_bfloat16 *p_w1h, *p_w1l, *p_w2h, *p_w2l, *p_w3h, *p_w3l;
    float* p_c3sk;
    cudaGetSymbolAddress((void**)&p_zh,  g_zh);  cudaGetSymbolAddress((void**)&p_zl,  g_zl);
    cudaGetSymbolAddress((void**)&p_c1h, g_c1h); cudaGetSymbolAddress((void**)&p_c1l, g_c1l);
    cudaGetSymbolAddress((void**)&p_c2h, g_c2h); cudaGetSymbolAddress((void**)&p_c2l, g_c2l);
    cudaGetSymbolAddress((void**)&p_w1h, g_w1h); cudaGetSymbolAddress((void**)&p_w1l, g_w1l);
    cudaGetSymbolAddress((void**)&p_w2h, g_w2h); cudaGetSymbolAddress((void**)&p_w2l, g_w2l);
    cudaGetSymbolAddress((void**)&p_w3h, g_w3h); cudaGetSymbolAddress((void**)&p_w3l, g_w3l);
    cudaGetSymbolAddress((void**)&p_c3sk, g_c3sk);

    k_init<<<1, 512>>>(la_a, la_b);
    k_wconv<<<1344, 256>>>(w1, w2, w3);
    k_conv<<<NB, 256>>>(x, la_bias);
    k_branch<<<NB, 256>>>(bn1_g, bn1_b, a1_w, a1_b, e1_w, e1_b,
                          f1_w, f1_b, fa_w, fa_b);
    k_zassm<<<NB, 256>>>(e2_w, e2_b, f2_w, f2_b, bn2_g, bn2_b, bn3_g, bn3_b);

    {   // GEMM1: 1024x1024x768, BM=128 -> grid 16x8 = 128 CTAs
        dim3 g(1024 / 64, NB / 128, 1);
        k_gemm_bf16<128, true><<<g, 256>>>(p_zh, p_zl, p_w1h, p_w1l, b1,
                                           p_c1h, p_c1l, nullptr,
                                           NB, 1024, 768, 768, 0);
    }
    {   // GEMM2: 1024x512x1024, BM=64 -> grid 8x16 = 128 CTAs
        dim3 g(512 / 64, NB / 64, 1);
        k_gemm_bf16<64, true><<<g, 256>>>(p_c1h, p_c1l, p_w2h, p_w2l, b2,
                                          p_c2h, p_c2l, nullptr,
                                          NB, 512, 1024, 1024, 0);
    }
    {   // GEMM3: 1024x128x512 split-K x4 -> 128 CTAs, fp32 partials
        dim3 g(128 / 64, NB / 64, 4);
        k_gemm_bf16<64, false><<<g, 256>>>(p_c2h, p_c2l, p_w3h, p_w3l, nullptr,
                                           nullptr, nullptr, p_c3sk,
                                           NB, 128, 512, 128, NB * 128);
    }
    k_fc4<<<NB / 8, 256>>>(w4, b4, b3, out);
}